// round 12
// baseline (speedup 1.0000x reference)
#include <cuda_runtime.h>
#include <cuda_fp16.h>
#include <math.h>
#include <stdint.h>

#define NB   4
#define NS   2048
#define ND   1024
#define NH   16
#define NDH  64
#define MT   (NB*NS)          // 8192 rows
#define QKV_ELEMS ((size_t)NB*NH*NS*NDH)
#define LOG2E 1.4426950408889634f

// ---------------- scratch (device globals: no allocation allowed) ----------
__device__ __half g_Qhf[QKV_ELEMS];           // post-RoPE, *0.125, fp16
__device__ __half g_Khf[QKV_ELEMS];
__device__ __half g_Vhf[QKV_ELEMS];
__device__ __half g_xhf[(size_t)MT*ND];
__device__ __half g_wqhf[(size_t)3*ND*ND];
__device__ __half g_wohf[(size_t)ND*ND];
__device__ __half g_ctxhf[(size_t)MT*ND];
__device__ float  g_freq[32];                 // 10000^(-i/32), fp32 (from double)

// ======================= helpers ===========================================
__device__ __forceinline__ uint32_t smem_u32(const void* p) {
    uint32_t a;
    asm("{ .reg .u64 t; cvta.to.shared.u64 t, %1; cvt.u32.u64 %0, t; }"
        : "=r"(a) : "l"(p));
    return a;
}
__device__ __forceinline__ void ldmx4(uint32_t addr, uint32_t r[4]) {
    asm volatile("ldmatrix.sync.aligned.m8n8.x4.shared.b16 {%0,%1,%2,%3}, [%4];"
                 : "=r"(r[0]), "=r"(r[1]), "=r"(r[2]), "=r"(r[3]) : "r"(addr));
}
__device__ __forceinline__ void ldmx4t(uint32_t addr, uint32_t r[4]) {
    asm volatile("ldmatrix.sync.aligned.m8n8.x4.trans.shared.b16 {%0,%1,%2,%3}, [%4];"
                 : "=r"(r[0]), "=r"(r[1]), "=r"(r[2]), "=r"(r[3]) : "r"(addr));
}
__device__ __forceinline__ void mma16816(float c[4], const uint32_t a[4],
                                         uint32_t b0, uint32_t b1) {
    asm("mma.sync.aligned.m16n8k16.row.col.f32.f16.f16.f32 "
        "{%0,%1,%2,%3}, {%4,%5,%6,%7}, {%8,%9}, {%0,%1,%2,%3};"
        : "+f"(c[0]), "+f"(c[1]), "+f"(c[2]), "+f"(c[3])
        : "r"(a[0]), "r"(a[1]), "r"(a[2]), "r"(a[3]), "r"(b0), "r"(b1));
}
__device__ __forceinline__ uint32_t packh2(float x, float y) {
    __half2 h = __floats2half2_rn(x, y);
    return *(uint32_t*)&h;
}
__device__ __forceinline__ uint32_t ex2h2(uint32_t x) {
    uint32_t d;
    asm("ex2.approx.f16x2 %0, %1;" : "=r"(d) : "r"(x));
    return d;
}
// XOR swizzle: 16B chunk c of 64B row
__device__ __forceinline__ uint32_t swz(int row, int c) {
    return (uint32_t)(row * 64 + ((c ^ ((row >> 1) & 3)) * 16));
}
// XOR swizzle for 128B rows
__device__ __forceinline__ uint32_t swz128(int row, int c) {
    return (uint32_t)(row * 128 + ((c ^ (row & 7)) * 16));
}
__device__ __forceinline__ void cpa16(uint32_t dst, const void* src) {
    asm volatile("cp.async.cg.shared.global [%0], [%1], 16;"
                 :: "r"(dst), "l"(src));
}
#define CP_COMMIT()  asm volatile("cp.async.commit_group;")
#define CP_WAIT(n)   asm volatile("cp.async.wait_group %0;" :: "n"(n))

// ===========================================================================
// setup: RoPE freqs (double-precision exp, matching jnp fp32-rounded values)
// ===========================================================================
__global__ void freq_kernel()
{
    int i = threadIdx.x;
    if (i < 32)
        g_freq[i] = (float)exp(-(double)i * (9.210340371976184 / 32.0));
}

// ===========================================================================
// merged fp32 -> fp16 converts for x, Wqkv, Wo
// ===========================================================================
__global__ void conv_all(const float4* __restrict__ x,
                         const float4* __restrict__ wq,
                         const float4* __restrict__ wo,
                         uint2* __restrict__ xh, uint2* __restrict__ wqh,
                         uint2* __restrict__ woh,
                         int n4x, int n4wq, int n4wo)
{
    int i = blockIdx.x * blockDim.x + threadIdx.x;
    const float4* src; uint2* dst; int idx;
    if (i < n4x)                 { src = x;  dst = xh;  idx = i; }
    else if (i < n4x + n4wq)     { src = wq; dst = wqh; idx = i - n4x; }
    else if (i < n4x + n4wq + n4wo) { src = wo; dst = woh; idx = i - n4x - n4wq; }
    else return;
    float4 v = src[idx];
    dst[idx] = make_uint2(packh2(v.x, v.y), packh2(v.z, v.w));
}

// ===========================================================================
// fp16 GEMM: CTA 128x128, 128 threads / 4 warps (2m x 2n), warp tile 64x64.
// cp.async 4-stage pipeline, K-chunk 32.
// EPI==0: fused QKV epilogue — RoPE(Q,K) -> fp16 (Q *0.125), V -> fp16.
// EPI==1: fp32 C.
// ===========================================================================
#define GSTG 16384
#define GK_SMEM (4*GSTG)

template<int EPI>
__global__ __launch_bounds__(128, 2) void gemm_f16(
    const __half* __restrict__ A, const __half* __restrict__ W,
    const float* __restrict__ bias, const int* __restrict__ posp,
    float* __restrict__ C, int N, int K)
{
    extern __shared__ char smc[];
    const uint32_t sb = smem_u32(smc);

    const int tid  = threadIdx.x;
    const int warp = tid >> 5, lane = tid & 31;
    const int wm2 = warp >> 1, wn = warp & 1;   // 2m x 2n warp grid
    const int m0 = blockIdx.y * 128, n0 = blockIdx.x * 128;

    // producer: 512 A-chunks + 512 W-chunks (16B), 128 threads -> 4+4 each
    uint32_t offs[4];
    const __half* pA[4];
    const __half* pW[4];
    #pragma unroll
    for (int j = 0; j < 4; j++) {
        int idx = tid + j * 128;            // 0..511
        int row = idx >> 2, c = idx & 3;
        offs[j] = swz(row, c);
        pA[j] = A + (size_t)(m0 + row) * K + c * 8;
        pW[j] = W + (size_t)(n0 + row) * K + c * 8;
    }

    float acc[4][8][4];
    #pragma unroll
    for (int mt = 0; mt < 4; mt++)
        #pragma unroll
        for (int nt = 0; nt < 8; nt++)
            #pragma unroll
            for (int i = 0; i < 4; i++) acc[mt][nt][i] = 0.f;

    uint32_t aOff[2][4], bOff[2][4];
    #pragma unroll
    for (int h = 0; h < 2; h++) {
        #pragma unroll
        for (int mt = 0; mt < 4; mt++) {
            int r = wm2 * 64 + mt * 16 + (lane & 15);
            int c = h * 2 + ((lane >> 4) & 1);
            aOff[h][mt] = swz(r, c);
        }
        #pragma unroll
        for (int ntp = 0; ntp < 4; ntp++) {
            int r = wn * 64 + ntp * 16 + (lane & 7) + ((lane >> 4) & 1) * 8;
            int c = h * 2 + ((lane >> 3) & 1);
            bOff[h][ntp] = swz(r, c);
        }
    }

    const int NSTG = K / 32;

    auto issue = [&](int s) {
        const uint32_t base = sb + (s & 3) * GSTG;
        const int k0 = s * 32;
        #pragma unroll
        for (int j = 0; j < 4; j++) {
            cpa16(base + offs[j],        pA[j] + k0);
            cpa16(base + 8192 + offs[j], pW[j] + k0);
        }
    };

    issue(0); CP_COMMIT();
    issue(1); CP_COMMIT();
    issue(2); CP_COMMIT();

    for (int s = 0; s < NSTG; s++) {
        CP_WAIT(2);
        __syncthreads();
        if (s + 3 < NSTG) issue(s + 3);
        CP_COMMIT();

        const uint32_t base = sb + (s & 3) * GSTG;
        #pragma unroll
        for (int h = 0; h < 2; h++) {
            uint32_t af[4][4];
            #pragma unroll
            for (int mt = 0; mt < 4; mt++)
                ldmx4(base + aOff[h][mt], af[mt]);
            #pragma unroll
            for (int ntp = 0; ntp < 4; ntp++) {
                uint32_t bfr[4];
                ldmx4(base + 8192 + bOff[h][ntp], bfr);
                #pragma unroll
                for (int mt = 0; mt < 4; mt++) {
                    mma16816(acc[mt][2*ntp],   af[mt], bfr[0], bfr[1]);
                    mma16816(acc[mt][2*ntp+1], af[mt], bfr[2], bfr[3]);
                }
            }
        }
    }

    // ---------------- epilogue ---------------------------------------------
    const int g = lane >> 2, tig = lane & 3;
    const int nBase = n0 + wn * 64;

    float bcol[8][2];
    #pragma unroll
    for (int nt = 0; nt < 8; nt++) {
        bcol[nt][0] = bias[nBase + nt * 8 + tig * 2];
        bcol[nt][1] = bias[nBase + nt * 8 + tig * 2 + 1];
    }

    if (EPI == 0) {
        int part = nBase >> 10;
        int hd   = (nBase & 1023) >> 6;
        if (part < 2) {
            __half* dst = part ? g_Khf : g_Qhf;
            const float sc = part ? 1.0f : 0.125f;
            float fr[4][2];
            #pragma unroll
            for (int nt = 0; nt < 4; nt++) {
                fr[nt][0] = g_freq[nt * 8 + tig * 2];
                fr[nt][1] = g_freq[nt * 8 + tig * 2 + 1];
            }
            #pragma unroll
            for (int mt = 0; mt < 4; mt++)
                #pragma unroll
                for (int half = 0; half < 2; half++) {
                    int m = m0 + wm2 * 64 + mt * 16 + g + half * 8;
                    int b = m >> 11, sq = m & 2047;
                    size_t rb = (((size_t)b * NH + hd) * NS + sq) * NDH;
                    float pos = (float)posp[b * NS + sq];
                    #pragma unroll
                    for (int nt = 0; nt < 4; nt++) {
                        float r1[2], r2[2];
                        #pragma unroll
                        for (int k = 0; k < 2; k++) {
                            float ang = pos * fr[nt][k];
                            float c, sn;
                            sincosf(ang, &sn, &c);
                            float q1 = acc[mt][nt][half*2 + k]   + bcol[nt][k];
                            float q2 = acc[mt][nt+4][half*2 + k] + bcol[nt+4][k];
                            r1[k] = (q1 * c + q2 * sn) * sc;
                            r2[k] = (q2 * c - q1 * sn) * sc;
                        }
                        int d = nt * 8 + tig * 2;
                        *(uint32_t*)((char*)dst + (rb + d) * 2)      = packh2(r1[0], r1[1]);
                        *(uint32_t*)((char*)dst + (rb + d + 32) * 2) = packh2(r2[0], r2[1]);
                    }
                }
        } else {
            #pragma unroll
            for (int mt = 0; mt < 4; mt++)
                #pragma unroll
                for (int half = 0; half < 2; half++) {
                    int m = m0 + wm2 * 64 + mt * 16 + g + half * 8;
                    int b = m >> 11, sq = m & 2047;
                    size_t rb = (((size_t)b * NH + hd) * NS + sq) * NDH;
                    #pragma unroll
                    for (int nt = 0; nt < 8; nt++) {
                        int d = nt * 8 + tig * 2;
                        float vx = acc[mt][nt][half*2]   + bcol[nt][0];
                        float vy = acc[mt][nt][half*2+1] + bcol[nt][1];
                        *(uint32_t*)((char*)g_Vhf + (rb + d) * 2) = packh2(vx, vy);
                    }
                }
        }
    } else {
        #pragma unroll
        for (int mt = 0; mt < 4; mt++)
            #pragma unroll
            for (int half = 0; half < 2; half++) {
                int m = m0 + wm2 * 64 + mt * 16 + g + half * 8;
                #pragma unroll
                for (int nt = 0; nt < 8; nt++) {
                    int n = nBase + nt * 8 + tig * 2;
                    float2 v;
                    v.x = acc[mt][nt][half*2]   + bcol[nt][0];
                    v.y = acc[mt][nt][half*2+1] + bcol[nt][1];
                    *(float2*)(C + (size_t)m * N + n) = v;
                }
            }
    }
}

// ===========================================================================
// fp16 flash attention (unchanged from passing R11): hoisted Q fragments,
// 3-stage cp.async KV ring, warp-vote rescale skip.
// ===========================================================================
#define AQ 0
#define ASTG_BASE 16384
#define ASTG 16384
#define AT_SMEM (ASTG_BASE + 3*ASTG)    // 65536
#define ONESH2 0x3C003C00u              // half2(1.0, 1.0)
#define NT (NS/64)                      // 32 kv tiles

__global__ __launch_bounds__(128, 2) void attn_f16()
{
    extern __shared__ char sma[];
    const uint32_t sb = smem_u32(sma);

    const int tid = threadIdx.x;
    const int warp = tid >> 5, lane = tid & 31;
    const int qt = blockIdx.x, bh = blockIdx.y;

    const size_t qbase  = ((size_t)bh * NS + qt * 128) * NDH;
    const size_t kvbase = (size_t)bh * NS * NDH;

    {
        #pragma unroll
        for (int j = 0; j < 8; j++) {
            int idx = tid + j * 128;
            int row = idx >> 3, c = idx & 7;
            cpa16(sb + AQ + swz128(row, c), g_Qhf + qbase + (size_t)row * NDH + c * 8);
        }
        CP_COMMIT();
    }

    const int rKV = tid >> 3, cKV = tid & 7;
    auto issue_kv = [&](int kt) {
        const uint32_t base = sb + ASTG_BASE + (kt % 3) * ASTG;
        #pragma unroll
        for (int j = 0; j < 4; j++) {
            int row = rKV + j * 16;
            uint32_t o = swz128(row, cKV);
            size_t go = kvbase + (size_t)(kt * 64 + row) * NDH + cKV * 8;
            cpa16(base + o,        g_Khf + go);
            cpa16(base + 8192 + o, g_Vhf + go);
        }
    };
    issue_kv(0); CP_COMMIT();
    issue_kv(1); CP_COMMIT();

    uint32_t qOff[4][2];
    #pragma unroll
    for (int kc = 0; kc < 4; kc++)
        #pragma unroll
        for (int mt = 0; mt < 2; mt++) {
            int r = warp * 32 + mt * 16 + (lane & 15);
            int c = kc * 2 + ((lane >> 4) & 1);
            qOff[kc][mt] = swz128(r, c);
        }
    uint32_t kOff[4][4];
    #pragma unroll
    for (int kc = 0; kc < 4; kc++)
        #pragma unroll
        for (int ntp = 0; ntp < 4; ntp++) {
            int r = ntp * 16 + (lane & 7) + ((lane >> 4) & 1) * 8;
            int c = kc * 2 + ((lane >> 3) & 1);
            kOff[kc][ntp] = swz128(r, c);
        }
    uint32_t vOff[4][4];
    #pragma unroll
    for (int kq = 0; kq < 4; kq++)
        #pragma unroll
        for (int dp = 0; dp < 4; dp++) {
            int r = kq * 16 + (lane & 7) + ((lane >> 3) & 1) * 8;
            int c = dp * 2 + ((lane >> 4) & 1);
            vOff[kq][dp] = swz128(r, c);
        }

    CP_WAIT(2);
    __syncthreads();
    uint32_t qf[4][2][4];
    #pragma unroll
    for (int kc = 0; kc < 4; kc++) {
        ldmx4(sb + AQ + qOff[kc][0], qf[kc][0]);
        ldmx4(sb + AQ + qOff[kc][1], qf[kc][1]);
    }

    float Oa[2][8][4];
    float lacc[2][4];
    float mrun[2][2];
    #pragma unroll
    for (int mt = 0; mt < 2; mt++) {
        mrun[mt][0] = -INFINITY; mrun[mt][1] = -INFINITY;
        #pragma unroll
        for (int i = 0; i < 4; i++) lacc[mt][i] = 0.f;
        #pragma unroll
        for (int dt = 0; dt < 8; dt++)
            #pragma unroll
            for (int i = 0; i < 4; i++) Oa[mt][dt][i] = 0.f;
    }

    for (int kt = 0; kt < NT; kt++) {
        if (kt + 1 < NT) { CP_WAIT(1); } else { CP_WAIT(0); }
        __syncthreads();
        if (kt + 2 < NT) { issue_kv(kt + 2); CP_COMMIT(); }

        const uint32_t kb = sb + ASTG_BASE + (kt % 3) * ASTG;

        float S[2][8][4];
        #pragma unroll
        for (int mt = 0; mt < 2; mt++)
            #pragma unroll
            for (int nt = 0; nt < 8; nt++)
                #pragma unroll
                for (int i = 0; i < 4; i++) S[mt][nt][i] = 0.f;

        #pragma unroll
        for (int kc = 0; kc < 4; kc++) {
            #pragma unroll
            for (int ntp = 0; ntp < 4; ntp++) {
                uint32_t kf[4];
                ldmx4(kb + kOff[kc][ntp], kf);
                mma16816(S[0][2*ntp],   qf[kc][0], kf[0], kf[1]);
                mma16816(S[0][2*ntp+1], qf[kc][0], kf[2], kf[3]);
                mma16816(S[1][2*ntp],   qf[kc][1], kf[0], kf[1]);
                mma16816(S[1][2*ntp+1], qf[kc][1], kf[2], kf[3]);
            }
        }

        uint32_t P2[2][8][2];
        #pragma unroll
        for (int mt = 0; mt < 2; mt++) {
            float mx0 = -INFINITY, mx1 = -INFINITY;
            #pragma unroll
            for (int j = 0; j < 8; j++) {
                mx0 = fmaxf(mx0, fmaxf(S[mt][j][0], S[mt][j][1]));
                mx1 = fmaxf(mx1, fmaxf(S[mt][j][2], S[mt][j][3]));
            }
            mx0 = fmaxf(mx0, __shfl_xor_sync(0xffffffffu, mx0, 1));
            mx0 = fmaxf(mx0, __shfl_xor_sync(0xffffffffu, mx0, 2));
            mx1 = fmaxf(mx1, __shfl_xor_sync(0xffffffffu, mx1, 1));
            mx1 = fmaxf(mx1, __shfl_xor_sync(0xffffffffu, mx1, 2));
            float nm0 = fmaxf(mrun[mt][0], mx0);
            float nm1 = fmaxf(mrun[mt][1], mx1);
            bool grew = (nm0 > mrun[mt][0]) || (nm1 > mrun[mt][1]);
            if (__any_sync(0xffffffffu, grew)) {
                float a0 = __expf(mrun[mt][0] - nm0);
                float a1 = __expf(mrun[mt][1] - nm1);
                #pragma unroll
                for (int dt = 0; dt < 8; dt++) {
                    Oa[mt][dt][0] *= a0; Oa[mt][dt][1] *= a0;
                    Oa[mt][dt][2] *= a1; Oa[mt][dt][3] *= a1;
                }
                lacc[mt][0] *= a0; lacc[mt][1] *= a0;
                lacc[mt][2] *= a1; lacc[mt][3] *= a1;
            }
            mrun[mt][0] = nm0; mrun[mt][1] = nm1;
            float nb0 = nm0 * LOG2E, nb1 = nm1 * LOG2E;
            #pragma unroll
            for (int j = 0; j < 8; j++) {
                float t0 = fmaf(S[mt][j][0], LOG2E, -nb0);
                float t1 = fmaf(S[mt][j][1], LOG2E, -nb0);
                P2[mt][j][0] = ex2h2(packh2(t0, t1));
                float t2 = fmaf(S[mt][j][2], LOG2E, -nb1);
                float t3 = fmaf(S[mt][j][3], LOG2E, -nb1);
                P2[mt][j][1] = ex2h2(packh2(t2, t3));
            }
        }

        #pragma unroll
        for (int kq = 0; kq < 4; kq++) {
            uint32_t pa0[4] = {P2[0][2*kq][0], P2[0][2*kq][1],
                               P2[0][2*kq+1][0], P2[0][2*kq+1][1]};
            uint32_t pa1[4] = {P2[1][2*kq][0], P2[1][2*kq][1],
                               P2[1][2*kq+1][0], P2[1][2*kq+1][1]};
            mma16816(lacc[0], pa0, ONESH2, ONESH2);
            mma16816(lacc[1], pa1, ONESH2, ONESH2);
            #pragma unroll
            for (int dp = 0; dp < 4; dp++) {
                uint32_t vf[4];
                ldmx4t(kb + 8192 + vOff[kq][dp], vf);
                mma16816(Oa[0][2*dp],   pa0, vf[0], vf[1]);
                mma16816(Oa[0][2*dp+1], pa0, vf[2], vf[3]);
                mma16816(Oa[1][2*dp],   pa1, vf[0], vf[1]);
                mma16816(Oa[1][2*dp+1], pa1, vf[2], vf[3]);
            }
        }
    }

    const int b = bh >> 4, h = bh & 15;
    const int g = lane >> 2, tg = lane & 3;
    #pragma unroll
    for (int mt = 0; mt < 2; mt++)
        #pragma unroll
        for (int half = 0; half < 2; half++) {
            int q = qt * 128 + warp * 32 + mt * 16 + g + half * 8;
            float inv = 1.0f / lacc[mt][half*2];
            size_t rb = ((size_t)b * NS + q) * ND + h * NDH;
            #pragma unroll
            for (int dt = 0; dt < 8; dt++) {
                float vx = Oa[mt][dt][half*2]   * inv;
                float vy = Oa[mt][dt][half*2+1] * inv;
                size_t o = rb + dt * 8 + tg * 2;
                *(uint32_t*)((char*)g_ctxhf + o * 2) = packh2(vx, vy);
            }
        }
}

// ===========================================================================
extern "C" void kernel_launch(void* const* d_in, const int* in_sizes, int n_in,
                              void* d_out, int out_size)
{
    (void)in_sizes; (void)n_in; (void)out_size;
    const float* x      = (const float*)d_in[0];
    const int*   p      = (const int*)d_in[1];
    const float* Wqkv_w = (const float*)d_in[2];
    const float* Wqkv_b = (const float*)d_in[3];
    const float* Wo_w   = (const float*)d_in[4];
    const float* Wo_b   = (const float*)d_in[5];
    float* out = (float*)d_out;

    cudaFuncSetAttribute(gemm_f16<0>,
                         cudaFuncAttributeMaxDynamicSharedMemorySize, GK_SMEM);
    cudaFuncSetAttribute(gemm_f16<1>,
                         cudaFuncAttributeMaxDynamicSharedMemorySize, GK_SMEM);
    cudaFuncSetAttribute(attn_f16,
                         cudaFuncAttributeMaxDynamicSharedMemorySize, AT_SMEM);

    __half *xh, *wqh, *woh, *ctxh;
    cudaGetSymbolAddress((void**)&xh,   g_xhf);
    cudaGetSymbolAddress((void**)&wqh,  g_wqhf);
    cudaGetSymbolAddress((void**)&woh,  g_wohf);
    cudaGetSymbolAddress((void**)&ctxh, g_ctxhf);

    freq_kernel<<<1, 32>>>();

    int n4x = MT * ND / 4, n4wq = 3 * ND * ND / 4, n4wo = ND * ND / 4;
    int n4t = n4x + n4wq + n4wo;
    conv_all<<<(n4t + 255) / 256, 256>>>(
        (const float4*)x, (const float4*)Wqkv_w, (const float4*)Wo_w,
        (uint2*)xh, (uint2*)wqh, (uint2*)woh, n4x, n4wq, n4wo);

    dim3 g1(3 * ND / 128, MT / 128);
    gemm_f16<0><<<g1, 128, GK_SMEM>>>(xh, wqh, Wqkv_b, p, nullptr, 3 * ND, ND);

    attn_f16<<<dim3(NS / 128, NB * NH), 128, AT_SMEM>>>();

    dim3 g2(ND / 128, MT / 128);
    gemm_f16<1><<<g2, 128, GK_SMEM>>>(ctxh, woh, Wo_b, nullptr, out, ND, ND);
}

// round 13
// speedup vs baseline: 1.0784x; 1.0784x over previous
#include <cuda_runtime.h>
#include <cuda_fp16.h>
#include <math.h>
#include <stdint.h>

#define NB   4
#define NS   2048
#define ND   1024
#define NH   16
#define NDH  64
#define MT   (NB*NS)          // 8192 rows
#define QKV_ELEMS ((size_t)NB*NH*NS*NDH)
#define LOG2E 1.4426950408889634f

// ---------------- scratch (device globals: no allocation allowed) ----------
__device__ __half g_Qhf[QKV_ELEMS];           // post-RoPE, *0.125, fp16
__device__ __half g_Khf[QKV_ELEMS];
__device__ __half g_Vhf[QKV_ELEMS];
__device__ __half g_xhf[(size_t)MT*ND];
__device__ __half g_wqhf[(size_t)3*ND*ND];
__device__ __half g_wohf[(size_t)ND*ND];
__device__ __half g_ctxhf[(size_t)MT*ND];
__device__ float  g_freq[32];                 // 10000^(-i/32), fp32 (from double)

// ======================= helpers ===========================================
__device__ __forceinline__ uint32_t smem_u32(const void* p) {
    uint32_t a;
    asm("{ .reg .u64 t; cvta.to.shared.u64 t, %1; cvt.u32.u64 %0, t; }"
        : "=r"(a) : "l"(p));
    return a;
}
__device__ __forceinline__ void ldmx4(uint32_t addr, uint32_t r[4]) {
    asm volatile("ldmatrix.sync.aligned.m8n8.x4.shared.b16 {%0,%1,%2,%3}, [%4];"
                 : "=r"(r[0]), "=r"(r[1]), "=r"(r[2]), "=r"(r[3]) : "r"(addr));
}
__device__ __forceinline__ void ldmx4t(uint32_t addr, uint32_t r[4]) {
    asm volatile("ldmatrix.sync.aligned.m8n8.x4.trans.shared.b16 {%0,%1,%2,%3}, [%4];"
                 : "=r"(r[0]), "=r"(r[1]), "=r"(r[2]), "=r"(r[3]) : "r"(addr));
}
__device__ __forceinline__ void mma16816(float c[4], const uint32_t a[4],
                                         uint32_t b0, uint32_t b1) {
    asm("mma.sync.aligned.m16n8k16.row.col.f32.f16.f16.f32 "
        "{%0,%1,%2,%3}, {%4,%5,%6,%7}, {%8,%9}, {%0,%1,%2,%3};"
        : "+f"(c[0]), "+f"(c[1]), "+f"(c[2]), "+f"(c[3])
        : "r"(a[0]), "r"(a[1]), "r"(a[2]), "r"(a[3]), "r"(b0), "r"(b1));
}
__device__ __forceinline__ uint32_t packh2(float x, float y) {
    __half2 h = __floats2half2_rn(x, y);
    return *(uint32_t*)&h;
}
__device__ __forceinline__ uint32_t ex2h2(uint32_t x) {
    uint32_t d;
    asm("ex2.approx.f16x2 %0, %1;" : "=r"(d) : "r"(x));
    return d;
}
// XOR swizzle for 128B rows: chunk c (0..7)
__device__ __forceinline__ uint32_t swz128(int row, int c) {
    return (uint32_t)(row * 128 + ((c ^ (row & 7)) * 16));
}
__device__ __forceinline__ void cpa16(uint32_t dst, const void* src) {
    asm volatile("cp.async.cg.shared.global [%0], [%1], 16;"
                 :: "r"(dst), "l"(src));
}
#define CP_COMMIT()  asm volatile("cp.async.commit_group;")
#define CP_WAIT(n)   asm volatile("cp.async.wait_group %0;" :: "n"(n))

// ===========================================================================
// setup: RoPE freqs (double-precision exp, matching jnp fp32-rounded values)
// ===========================================================================
__global__ void freq_kernel()
{
    int i = threadIdx.x;
    if (i < 32)
        g_freq[i] = (float)exp(-(double)i * (9.210340371976184 / 32.0));
}

// ===========================================================================
// merged fp32 -> fp16 converts for x, Wqkv, Wo
// ===========================================================================
__global__ void conv_all(const float4* __restrict__ x,
                         const float4* __restrict__ wq,
                         const float4* __restrict__ wo,
                         uint2* __restrict__ xh, uint2* __restrict__ wqh,
                         uint2* __restrict__ woh,
                         int n4x, int n4wq, int n4wo)
{
    int i = blockIdx.x * blockDim.x + threadIdx.x;
    const float4* src; uint2* dst; int idx;
    if (i < n4x)                 { src = x;  dst = xh;  idx = i; }
    else if (i < n4x + n4wq)     { src = wq; dst = wqh; idx = i - n4x; }
    else if (i < n4x + n4wq + n4wo) { src = wo; dst = woh; idx = i - n4x - n4wq; }
    else return;
    float4 v = src[idx];
    dst[idx] = make_uint2(packh2(v.x, v.y), packh2(v.z, v.w));
}

// ===========================================================================
// fp16 GEMM: CTA 128x128, 256 threads / 8 warps (4m x 2n, warp tile 32x64 —
// the proven R11 shape). K-chunk 64 per stage (128B rows, swz128),
// 3-stage cp.async ring (96KB smem, occ 2). Half the barriers of R11.
// EPI==0: fused QKV epilogue — RoPE(Q,K) -> fp16 (Q *0.125), V -> fp16.
// EPI==1: fp32 C.
// ===========================================================================
#define GSTG 32768
#define GK_SMEM (3*GSTG)     // 98304

template<int EPI>
__global__ __launch_bounds__(256, 2) void gemm_f16(
    const __half* __restrict__ A, const __half* __restrict__ W,
    const float* __restrict__ bias, const int* __restrict__ posp,
    float* __restrict__ C, int N, int K)
{
    extern __shared__ char smc[];
    const uint32_t sb = smem_u32(smc);

    const int tid  = threadIdx.x;
    const int warp = tid >> 5, lane = tid & 31;
    const int wm = warp & 3, cg = warp >> 2;
    const int m0 = blockIdx.y * 128, n0 = blockIdx.x * 128;

    // producer: per stage, A: 128 rows x 8 chunks = 1024 + W: 1024 chunks
    // of 16B; 256 threads -> 4 A + 4 W each
    uint32_t offs[4];
    const __half* pA[4];
    const __half* pW[4];
    #pragma unroll
    for (int j = 0; j < 4; j++) {
        int idx = tid + j * 256;            // 0..1023
        int row = idx >> 3, c = idx & 7;
        offs[j] = swz128(row, c);
        pA[j] = A + (size_t)(m0 + row) * K + c * 8;
        pW[j] = W + (size_t)(n0 + row) * K + c * 8;
    }

    float acc[2][8][4];
    #pragma unroll
    for (int mt = 0; mt < 2; mt++)
        #pragma unroll
        for (int nt = 0; nt < 8; nt++)
            #pragma unroll
            for (int i = 0; i < 4; i++) acc[mt][nt][i] = 0.f;

    // fragment offsets: kc = k16-half within stage (0..3)
    uint32_t aOff[4][2], bOff[4][4];
    #pragma unroll
    for (int kc = 0; kc < 4; kc++) {
        #pragma unroll
        for (int mt = 0; mt < 2; mt++) {
            int r = wm * 32 + mt * 16 + (lane & 15);
            int c = kc * 2 + ((lane >> 4) & 1);
            aOff[kc][mt] = swz128(r, c);
        }
        #pragma unroll
        for (int ntp = 0; ntp < 4; ntp++) {
            int r = cg * 64 + ntp * 16 + (lane & 7) + ((lane >> 4) & 1) * 8;
            int c = kc * 2 + ((lane >> 3) & 1);
            bOff[kc][ntp] = swz128(r, c);
        }
    }

    const int NSTG = K / 64;

    auto issue = [&](int s) {
        const uint32_t base = sb + (s % 3) * GSTG;
        const int k0 = s * 64;
        #pragma unroll
        for (int j = 0; j < 4; j++) {
            cpa16(base + offs[j],         pA[j] + k0);
            cpa16(base + 16384 + offs[j], pW[j] + k0);
        }
    };

    issue(0); CP_COMMIT();
    issue(1); CP_COMMIT();

    for (int s = 0; s < NSTG; s++) {
        if (s + 1 < NSTG) { CP_WAIT(1); } else { CP_WAIT(0); }
        __syncthreads();
        if (s + 2 < NSTG) { issue(s + 2); CP_COMMIT(); }

        const uint32_t base = sb + (s % 3) * GSTG;
        #pragma unroll
        for (int kc = 0; kc < 4; kc++) {
            uint32_t a0[4], a1[4];
            ldmx4(base + aOff[kc][0], a0);
            ldmx4(base + aOff[kc][1], a1);
            #pragma unroll
            for (int ntp = 0; ntp < 4; ntp++) {
                uint32_t bfr[4];
                ldmx4(base + 16384 + bOff[kc][ntp], bfr);
                mma16816(acc[0][2*ntp],   a0, bfr[0], bfr[1]);
                mma16816(acc[0][2*ntp+1], a0, bfr[2], bfr[3]);
                mma16816(acc[1][2*ntp],   a1, bfr[0], bfr[1]);
                mma16816(acc[1][2*ntp+1], a1, bfr[2], bfr[3]);
            }
        }
    }

    // ---------------- epilogue (identical to R11) --------------------------
    const int g = lane >> 2, tig = lane & 3;
    const int nBase = n0 + cg * 64;

    float bcol[8][2];
    #pragma unroll
    for (int nt = 0; nt < 8; nt++) {
        bcol[nt][0] = bias[nBase + nt * 8 + tig * 2];
        bcol[nt][1] = bias[nBase + nt * 8 + tig * 2 + 1];
    }

    if (EPI == 0) {
        int part = nBase >> 10;
        int hd   = (nBase & 1023) >> 6;
        if (part < 2) {
            __half* dst = part ? g_Khf : g_Qhf;
            const float sc = part ? 1.0f : 0.125f;
            float fr[4][2];
            #pragma unroll
            for (int nt = 0; nt < 4; nt++) {
                fr[nt][0] = g_freq[nt * 8 + tig * 2];
                fr[nt][1] = g_freq[nt * 8 + tig * 2 + 1];
            }
            #pragma unroll
            for (int mt = 0; mt < 2; mt++)
                #pragma unroll
                for (int half = 0; half < 2; half++) {
                    int m = m0 + wm * 32 + mt * 16 + g + half * 8;
                    int b = m >> 11, sq = m & 2047;
                    size_t rb = (((size_t)b * NH + hd) * NS + sq) * NDH;
                    float pos = (float)posp[b * NS + sq];
                    #pragma unroll
                    for (int nt = 0; nt < 4; nt++) {
                        float r1[2], r2[2];
                        #pragma unroll
                        for (int k = 0; k < 2; k++) {
                            float ang = pos * fr[nt][k];
                            float c, sn;
                            sincosf(ang, &sn, &c);
                            float q1 = acc[mt][nt][half*2 + k]   + bcol[nt][k];
                            float q2 = acc[mt][nt+4][half*2 + k] + bcol[nt+4][k];
                            r1[k] = (q1 * c + q2 * sn) * sc;
                            r2[k] = (q2 * c - q1 * sn) * sc;
                        }
                        int d = nt * 8 + tig * 2;
                        *(uint32_t*)((char*)dst + (rb + d) * 2)      = packh2(r1[0], r1[1]);
                        *(uint32_t*)((char*)dst + (rb + d + 32) * 2) = packh2(r2[0], r2[1]);
                    }
                }
        } else {
            #pragma unroll
            for (int mt = 0; mt < 2; mt++)
                #pragma unroll
                for (int half = 0; half < 2; half++) {
                    int m = m0 + wm * 32 + mt * 16 + g + half * 8;
                    int b = m >> 11, sq = m & 2047;
                    size_t rb = (((size_t)b * NH + hd) * NS + sq) * NDH;
                    #pragma unroll
                    for (int nt = 0; nt < 8; nt++) {
                        int d = nt * 8 + tig * 2;
                        float vx = acc[mt][nt][half*2]   + bcol[nt][0];
                        float vy = acc[mt][nt][half*2+1] + bcol[nt][1];
                        *(uint32_t*)((char*)g_Vhf + (rb + d) * 2) = packh2(vx, vy);
                    }
                }
        }
    } else {
        #pragma unroll
        for (int mt = 0; mt < 2; mt++)
            #pragma unroll
            for (int half = 0; half < 2; half++) {
                int m = m0 + wm * 32 + mt * 16 + g + half * 8;
                #pragma unroll
                for (int nt = 0; nt < 8; nt++) {
                    int n = nBase + nt * 8 + tig * 2;
                    float2 v;
                    v.x = acc[mt][nt][half*2]   + bcol[nt][0];
                    v.y = acc[mt][nt][half*2+1] + bcol[nt][1];
                    *(float2*)(C + (size_t)m * N + n) = v;
                }
            }
    }
}

// ===========================================================================
// fp16 flash attention (unchanged from passing R11): hoisted Q fragments,
// 3-stage cp.async KV ring, warp-vote rescale skip.
// ===========================================================================
#define AQ 0
#define ASTG_BASE 16384
#define ASTG 16384
#define AT_SMEM (ASTG_BASE + 3*ASTG)    // 65536
#define ONESH2 0x3C003C00u              // half2(1.0, 1.0)
#define NT (NS/64)                      // 32 kv tiles

__global__ __launch_bounds__(128, 2) void attn_f16()
{
    extern __shared__ char sma[];
    const uint32_t sb = smem_u32(sma);

    const int tid = threadIdx.x;
    const int warp = tid >> 5, lane = tid & 31;
    const int qt = blockIdx.x, bh = blockIdx.y;

    const size_t qbase  = ((size_t)bh * NS + qt * 128) * NDH;
    const size_t kvbase = (size_t)bh * NS * NDH;

    {
        #pragma unroll
        for (int j = 0; j < 8; j++) {
            int idx = tid + j * 128;
            int row = idx >> 3, c = idx & 7;
            cpa16(sb + AQ + swz128(row, c), g_Qhf + qbase + (size_t)row * NDH + c * 8);
        }
        CP_COMMIT();
    }

    const int rKV = tid >> 3, cKV = tid & 7;
    auto issue_kv = [&](int kt) {
        const uint32_t base = sb + ASTG_BASE + (kt % 3) * ASTG;
        #pragma unroll
        for (int j = 0; j < 4; j++) {
            int row = rKV + j * 16;
            uint32_t o = swz128(row, cKV);
            size_t go = kvbase + (size_t)(kt * 64 + row) * NDH + cKV * 8;
            cpa16(base + o,        g_Khf + go);
            cpa16(base + 8192 + o, g_Vhf + go);
        }
    };
    issue_kv(0); CP_COMMIT();
    issue_kv(1); CP_COMMIT();

    uint32_t qOff[4][2];
    #pragma unroll
    for (int kc = 0; kc < 4; kc++)
        #pragma unroll
        for (int mt = 0; mt < 2; mt++) {
            int r = warp * 32 + mt * 16 + (lane & 15);
            int c = kc * 2 + ((lane >> 4) & 1);
            qOff[kc][mt] = swz128(r, c);
        }
    uint32_t kOff[4][4];
    #pragma unroll
    for (int kc = 0; kc < 4; kc++)
        #pragma unroll
        for (int ntp = 0; ntp < 4; ntp++) {
            int r = ntp * 16 + (lane & 7) + ((lane >> 4) & 1) * 8;
            int c = kc * 2 + ((lane >> 3) & 1);
            kOff[kc][ntp] = swz128(r, c);
        }
    uint32_t vOff[4][4];
    #pragma unroll
    for (int kq = 0; kq < 4; kq++)
        #pragma unroll
        for (int dp = 0; dp < 4; dp++) {
            int r = kq * 16 + (lane & 7) + ((lane >> 3) & 1) * 8;
            int c = dp * 2 + ((lane >> 4) & 1);
            vOff[kq][dp] = swz128(r, c);
        }

    CP_WAIT(2);
    __syncthreads();
    uint32_t qf[4][2][4];
    #pragma unroll
    for (int kc = 0; kc < 4; kc++) {
        ldmx4(sb + AQ + qOff[kc][0], qf[kc][0]);
        ldmx4(sb + AQ + qOff[kc][1], qf[kc][1]);
    }

    float Oa[2][8][4];
    float lacc[2][4];
    float mrun[2][2];
    #pragma unroll
    for (int mt = 0; mt < 2; mt++) {
        mrun[mt][0] = -INFINITY; mrun[mt][1] = -INFINITY;
        #pragma unroll
        for (int i = 0; i < 4; i++) lacc[mt][i] = 0.f;
        #pragma unroll
        for (int dt = 0; dt < 8; dt++)
            #pragma unroll
            for (int i = 0; i < 4; i++) Oa[mt][dt][i] = 0.f;
    }

    for (int kt = 0; kt < NT; kt++) {
        if (kt + 1 < NT) { CP_WAIT(1); } else { CP_WAIT(0); }
        __syncthreads();
        if (kt + 2 < NT) { issue_kv(kt + 2); CP_COMMIT(); }

        const uint32_t kb = sb + ASTG_BASE + (kt % 3) * ASTG;

        float S[2][8][4];
        #pragma unroll
        for (int mt = 0; mt < 2; mt++)
            #pragma unroll
            for (int nt = 0; nt < 8; nt++)
                #pragma unroll
                for (int i = 0; i < 4; i++) S[mt][nt][i] = 0.f;

        #pragma unroll
        for (int kc = 0; kc < 4; kc++) {
            #pragma unroll
            for (int ntp = 0; ntp < 4; ntp++) {
                uint32_t kf[4];
                ldmx4(kb + kOff[kc][ntp], kf);
                mma16816(S[0][2*ntp],   qf[kc][0], kf[0], kf[1]);
                mma16816(S[0][2*ntp+1], qf[kc][0], kf[2], kf[3]);
                mma16816(S[1][2*ntp],   qf[kc][1], kf[0], kf[1]);
                mma16816(S[1][2*ntp+1], qf[kc][1], kf[2], kf[3]);
            }
        }

        uint32_t P2[2][8][2];
        #pragma unroll
        for (int mt = 0; mt < 2; mt++) {
            float mx0 = -INFINITY, mx1 = -INFINITY;
            #pragma unroll
            for (int j = 0; j < 8; j++) {
                mx0 = fmaxf(mx0, fmaxf(S[mt][j][0], S[mt][j][1]));
                mx1 = fmaxf(mx1, fmaxf(S[mt][j][2], S[mt][j][3]));
            }
            mx0 = fmaxf(mx0, __shfl_xor_sync(0xffffffffu, mx0, 1));
            mx0 = fmaxf(mx0, __shfl_xor_sync(0xffffffffu, mx0, 2));
            mx1 = fmaxf(mx1, __shfl_xor_sync(0xffffffffu, mx1, 1));
            mx1 = fmaxf(mx1, __shfl_xor_sync(0xffffffffu, mx1, 2));
            float nm0 = fmaxf(mrun[mt][0], mx0);
            float nm1 = fmaxf(mrun[mt][1], mx1);
            bool grew = (nm0 > mrun[mt][0]) || (nm1 > mrun[mt][1]);
            if (__any_sync(0xffffffffu, grew)) {
                float a0 = __expf(mrun[mt][0] - nm0);
                float a1 = __expf(mrun[mt][1] - nm1);
                #pragma unroll
                for (int dt = 0; dt < 8; dt++) {
                    Oa[mt][dt][0] *= a0; Oa[mt][dt][1] *= a0;
                    Oa[mt][dt][2] *= a1; Oa[mt][dt][3] *= a1;
                }
                lacc[mt][0] *= a0; lacc[mt][1] *= a0;
                lacc[mt][2] *= a1; lacc[mt][3] *= a1;
            }
            mrun[mt][0] = nm0; mrun[mt][1] = nm1;
            float nb0 = nm0 * LOG2E, nb1 = nm1 * LOG2E;
            #pragma unroll
            for (int j = 0; j < 8; j++) {
                float t0 = fmaf(S[mt][j][0], LOG2E, -nb0);
                float t1 = fmaf(S[mt][j][1], LOG2E, -nb0);
                P2[mt][j][0] = ex2h2(packh2(t0, t1));
                float t2 = fmaf(S[mt][j][2], LOG2E, -nb1);
                float t3 = fmaf(S[mt][j][3], LOG2E, -nb1);
                P2[mt][j][1] = ex2h2(packh2(t2, t3));
            }
        }

        #pragma unroll
        for (int kq = 0; kq < 4; kq++) {
            uint32_t pa0[4] = {P2[0][2*kq][0], P2[0][2*kq][1],
                               P2[0][2*kq+1][0], P2[0][2*kq+1][1]};
            uint32_t pa1[4] = {P2[1][2*kq][0], P2[1][2*kq][1],
                               P2[1][2*kq+1][0], P2[1][2*kq+1][1]};
            mma16816(lacc[0], pa0, ONESH2, ONESH2);
            mma16816(lacc[1], pa1, ONESH2, ONESH2);
            #pragma unroll
            for (int dp = 0; dp < 4; dp++) {
                uint32_t vf[4];
                ldmx4t(kb + 8192 + vOff[kq][dp], vf);
                mma16816(Oa[0][2*dp],   pa0, vf[0], vf[1]);
                mma16816(Oa[0][2*dp+1], pa0, vf[2], vf[3]);
                mma16816(Oa[1][2*dp],   pa1, vf[0], vf[1]);
                mma16816(Oa[1][2*dp+1], pa1, vf[2], vf[3]);
            }
        }
    }

    const int b = bh >> 4, h = bh & 15;
    const int g = lane >> 2, tg = lane & 3;
    #pragma unroll
    for (int mt = 0; mt < 2; mt++)
        #pragma unroll
        for (int half = 0; half < 2; half++) {
            int q = qt * 128 + warp * 32 + mt * 16 + g + half * 8;
            float inv = 1.0f / lacc[mt][half*2];
            size_t rb = ((size_t)b * NS + q) * ND + h * NDH;
            #pragma unroll
            for (int dt = 0; dt < 8; dt++) {
                float vx = Oa[mt][dt][half*2]   * inv;
                float vy = Oa[mt][dt][half*2+1] * inv;
                size_t o = rb + dt * 8 + tg * 2;
                *(uint32_t*)((char*)g_ctxhf + o * 2) = packh2(vx, vy);
            }
        }
}

// ===========================================================================
extern "C" void kernel_launch(void* const* d_in, const int* in_sizes, int n_in,
                              void* d_out, int out_size)
{
    (void)in_sizes; (void)n_in; (void)out_size;
    const float* x      = (const float*)d_in[0];
    const int*   p      = (const int*)d_in[1];
    const float* Wqkv_w = (const float*)d_in[2];
    const float* Wqkv_b = (const float*)d_in[3];
    const float* Wo_w   = (const float*)d_in[4];
    const float* Wo_b   = (const float*)d_in[5];
    float* out = (float*)d_out;

    cudaFuncSetAttribute(gemm_f16<0>,
                         cudaFuncAttributeMaxDynamicSharedMemorySize, GK_SMEM);
    cudaFuncSetAttribute(gemm_f16<1>,
                         cudaFuncAttributeMaxDynamicSharedMemorySize, GK_SMEM);
    cudaFuncSetAttribute(attn_f16,
                         cudaFuncAttributeMaxDynamicSharedMemorySize, AT_SMEM);

    __half *xh, *wqh, *woh, *ctxh;
    cudaGetSymbolAddress((void**)&xh,   g_xhf);
    cudaGetSymbolAddress((void**)&wqh,  g_wqhf);
    cudaGetSymbolAddress((void**)&woh,  g_wohf);
    cudaGetSymbolAddress((void**)&ctxh, g_ctxhf);

    freq_kernel<<<1, 32>>>();

    int n4x = MT * ND / 4, n4wq = 3 * ND * ND / 4, n4wo = ND * ND / 4;
    int n4t = n4x + n4wq + n4wo;
    conv_all<<<(n4t + 255) / 256, 256>>>(
        (const float4*)x, (const float4*)Wqkv_w, (const float4*)Wo_w,
        (uint2*)xh, (uint2*)wqh, (uint2*)woh, n4x, n4wq, n4wo);

    dim3 g1(3 * ND / 128, MT / 128);
    gemm_f16<0><<<g1, 256, GK_SMEM>>>(xh, wqh, Wqkv_b, p, nullptr, 3 * ND, ND);

    attn_f16<<<dim3(NS / 128, NB * NH), 128, AT_SMEM>>>();

    dim3 g2(ND / 128, MT / 128);
    gemm_f16<1><<<g2, 256, GK_SMEM>>>(ctxh, woh, Wo_b, nullptr, out, ND, ND);
}

// round 14
// speedup vs baseline: 1.0863x; 1.0073x over previous
#include <cuda_runtime.h>
#include <cuda_fp16.h>
#include <math.h>
#include <stdint.h>

#define NB   4
#define NS   2048
#define ND   1024
#define NH   16
#define NDH  64
#define MT   (NB*NS)          // 8192 rows
#define QKV_ELEMS ((size_t)NB*NH*NS*NDH)
#define LOG2E 1.4426950408889634f

// ---------------- scratch (device globals: no allocation allowed) ----------
__device__ __half g_Qhf[QKV_ELEMS];           // post-RoPE, *0.125, fp16
__device__ __half g_Khf[QKV_ELEMS];
__device__ __half g_Vhf[QKV_ELEMS];
__device__ __half g_xhf[(size_t)MT*ND];
__device__ __half g_wqhf[(size_t)3*ND*ND];
__device__ __half g_wohf[(size_t)ND*ND];
__device__ __half g_ctxhf[(size_t)MT*ND];
__device__ float  g_freq[32];                 // 10000^(-i/32), fp32 (from double)

// ======================= helpers ===========================================
__device__ __forceinline__ uint32_t smem_u32(const void* p) {
    uint32_t a;
    asm("{ .reg .u64 t; cvta.to.shared.u64 t, %1; cvt.u32.u64 %0, t; }"
        : "=r"(a) : "l"(p));
    return a;
}
__device__ __forceinline__ void ldmx4(uint32_t addr, uint32_t r[4]) {
    asm volatile("ldmatrix.sync.aligned.m8n8.x4.shared.b16 {%0,%1,%2,%3}, [%4];"
                 : "=r"(r[0]), "=r"(r[1]), "=r"(r[2]), "=r"(r[3]) : "r"(addr));
}
__device__ __forceinline__ void ldmx4t(uint32_t addr, uint32_t r[4]) {
    asm volatile("ldmatrix.sync.aligned.m8n8.x4.trans.shared.b16 {%0,%1,%2,%3}, [%4];"
                 : "=r"(r[0]), "=r"(r[1]), "=r"(r[2]), "=r"(r[3]) : "r"(addr));
}
__device__ __forceinline__ void mma16816(float c[4], const uint32_t a[4],
                                         uint32_t b0, uint32_t b1) {
    asm("mma.sync.aligned.m16n8k16.row.col.f32.f16.f16.f32 "
        "{%0,%1,%2,%3}, {%4,%5,%6,%7}, {%8,%9}, {%0,%1,%2,%3};"
        : "+f"(c[0]), "+f"(c[1]), "+f"(c[2]), "+f"(c[3])
        : "r"(a[0]), "r"(a[1]), "r"(a[2]), "r"(a[3]), "r"(b0), "r"(b1));
}
__device__ __forceinline__ uint32_t packh2(float x, float y) {
    __half2 h = __floats2half2_rn(x, y);
    return *(uint32_t*)&h;
}
__device__ __forceinline__ uint32_t ex2h2(uint32_t x) {
    uint32_t d;
    asm("ex2.approx.f16x2 %0, %1;" : "=r"(d) : "r"(x));
    return d;
}
// XOR swizzle for 128B rows: chunk c (0..7)
__device__ __forceinline__ uint32_t swz128(int row, int c) {
    return (uint32_t)(row * 128 + ((c ^ (row & 7)) * 16));
}
__device__ __forceinline__ void cpa16(uint32_t dst, const void* src) {
    asm volatile("cp.async.cg.shared.global [%0], [%1], 16;"
                 :: "r"(dst), "l"(src));
}
#define CP_COMMIT()  asm volatile("cp.async.commit_group;")
#define CP_WAIT(n)   asm volatile("cp.async.wait_group %0;" :: "n"(n))

// ===========================================================================
// setup: RoPE freqs (double-precision exp, matching jnp fp32-rounded values)
// ===========================================================================
__global__ void freq_kernel()
{
    int i = threadIdx.x;
    if (i < 32)
        g_freq[i] = (float)exp(-(double)i * (9.210340371976184 / 32.0));
}

// ===========================================================================
// merged fp32 -> fp16 converts for x, Wqkv, Wo
// ===========================================================================
__global__ void conv_all(const float4* __restrict__ x,
                         const float4* __restrict__ wq,
                         const float4* __restrict__ wo,
                         uint2* __restrict__ xh, uint2* __restrict__ wqh,
                         uint2* __restrict__ woh,
                         int n4x, int n4wq, int n4wo)
{
    int i = blockIdx.x * blockDim.x + threadIdx.x;
    const float4* src; uint2* dst; int idx;
    if (i < n4x)                 { src = x;  dst = xh;  idx = i; }
    else if (i < n4x + n4wq)     { src = wq; dst = wqh; idx = i - n4x; }
    else if (i < n4x + n4wq + n4wo) { src = wo; dst = woh; idx = i - n4x - n4wq; }
    else return;
    float4 v = src[idx];
    dst[idx] = make_uint2(packh2(v.x, v.y), packh2(v.z, v.w));
}

// ===========================================================================
// fp16 GEMM (unchanged from passing R13): 256 thr / 8 warps, warp tile 32x64,
// K-chunk 64 per stage (128B rows), 3-stage cp.async ring (96KB, occ 2).
// EPI==0: fused QKV epilogue — RoPE(Q,K) -> fp16 (Q *0.125), V -> fp16.
// EPI==1: fp32 C.
// ===========================================================================
#define GSTG 32768
#define GK_SMEM (3*GSTG)     // 98304

template<int EPI>
__global__ __launch_bounds__(256, 2) void gemm_f16(
    const __half* __restrict__ A, const __half* __restrict__ W,
    const float* __restrict__ bias, const int* __restrict__ posp,
    float* __restrict__ C, int N, int K)
{
    extern __shared__ char smc[];
    const uint32_t sb = smem_u32(smc);

    const int tid  = threadIdx.x;
    const int warp = tid >> 5, lane = tid & 31;
    const int wm = warp & 3, cg = warp >> 2;
    const int m0 = blockIdx.y * 128, n0 = blockIdx.x * 128;

    uint32_t offs[4];
    const __half* pA[4];
    const __half* pW[4];
    #pragma unroll
    for (int j = 0; j < 4; j++) {
        int idx = tid + j * 256;
        int row = idx >> 3, c = idx & 7;
        offs[j] = swz128(row, c);
        pA[j] = A + (size_t)(m0 + row) * K + c * 8;
        pW[j] = W + (size_t)(n0 + row) * K + c * 8;
    }

    float acc[2][8][4];
    #pragma unroll
    for (int mt = 0; mt < 2; mt++)
        #pragma unroll
        for (int nt = 0; nt < 8; nt++)
            #pragma unroll
            for (int i = 0; i < 4; i++) acc[mt][nt][i] = 0.f;

    uint32_t aOff[4][2], bOff[4][4];
    #pragma unroll
    for (int kc = 0; kc < 4; kc++) {
        #pragma unroll
        for (int mt = 0; mt < 2; mt++) {
            int r = wm * 32 + mt * 16 + (lane & 15);
            int c = kc * 2 + ((lane >> 4) & 1);
            aOff[kc][mt] = swz128(r, c);
        }
        #pragma unroll
        for (int ntp = 0; ntp < 4; ntp++) {
            int r = cg * 64 + ntp * 16 + (lane & 7) + ((lane >> 4) & 1) * 8;
            int c = kc * 2 + ((lane >> 3) & 1);
            bOff[kc][ntp] = swz128(r, c);
        }
    }

    const int NSTG = K / 64;

    auto issue = [&](int s) {
        const uint32_t base = sb + (s % 3) * GSTG;
        const int k0 = s * 64;
        #pragma unroll
        for (int j = 0; j < 4; j++) {
            cpa16(base + offs[j],         pA[j] + k0);
            cpa16(base + 16384 + offs[j], pW[j] + k0);
        }
    };

    issue(0); CP_COMMIT();
    issue(1); CP_COMMIT();

    for (int s = 0; s < NSTG; s++) {
        if (s + 1 < NSTG) { CP_WAIT(1); } else { CP_WAIT(0); }
        __syncthreads();
        if (s + 2 < NSTG) { issue(s + 2); CP_COMMIT(); }

        const uint32_t base = sb + (s % 3) * GSTG;
        #pragma unroll
        for (int kc = 0; kc < 4; kc++) {
            uint32_t a0[4], a1[4];
            ldmx4(base + aOff[kc][0], a0);
            ldmx4(base + aOff[kc][1], a1);
            #pragma unroll
            for (int ntp = 0; ntp < 4; ntp++) {
                uint32_t bfr[4];
                ldmx4(base + 16384 + bOff[kc][ntp], bfr);
                mma16816(acc[0][2*ntp],   a0, bfr[0], bfr[1]);
                mma16816(acc[0][2*ntp+1], a0, bfr[2], bfr[3]);
                mma16816(acc[1][2*ntp],   a1, bfr[0], bfr[1]);
                mma16816(acc[1][2*ntp+1], a1, bfr[2], bfr[3]);
            }
        }
    }

    // ---------------- epilogue ---------------------------------------------
    const int g = lane >> 2, tig = lane & 3;
    const int nBase = n0 + cg * 64;

    float bcol[8][2];
    #pragma unroll
    for (int nt = 0; nt < 8; nt++) {
        bcol[nt][0] = bias[nBase + nt * 8 + tig * 2];
        bcol[nt][1] = bias[nBase + nt * 8 + tig * 2 + 1];
    }

    if (EPI == 0) {
        int part = nBase >> 10;
        int hd   = (nBase & 1023) >> 6;
        if (part < 2) {
            __half* dst = part ? g_Khf : g_Qhf;
            const float sc = part ? 1.0f : 0.125f;
            float fr[4][2];
            #pragma unroll
            for (int nt = 0; nt < 4; nt++) {
                fr[nt][0] = g_freq[nt * 8 + tig * 2];
                fr[nt][1] = g_freq[nt * 8 + tig * 2 + 1];
            }
            #pragma unroll
            for (int mt = 0; mt < 2; mt++)
                #pragma unroll
                for (int half = 0; half < 2; half++) {
                    int m = m0 + wm * 32 + mt * 16 + g + half * 8;
                    int b = m >> 11, sq = m & 2047;
                    size_t rb = (((size_t)b * NH + hd) * NS + sq) * NDH;
                    float pos = (float)posp[b * NS + sq];
                    #pragma unroll
                    for (int nt = 0; nt < 4; nt++) {
                        float r1[2], r2[2];
                        #pragma unroll
                        for (int k = 0; k < 2; k++) {
                            float ang = pos * fr[nt][k];
                            float c, sn;
                            sincosf(ang, &sn, &c);
                            float q1 = acc[mt][nt][half*2 + k]   + bcol[nt][k];
                            float q2 = acc[mt][nt+4][half*2 + k] + bcol[nt+4][k];
                            r1[k] = (q1 * c + q2 * sn) * sc;
                            r2[k] = (q2 * c - q1 * sn) * sc;
                        }
                        int d = nt * 8 + tig * 2;
                        *(uint32_t*)((char*)dst + (rb + d) * 2)      = packh2(r1[0], r1[1]);
                        *(uint32_t*)((char*)dst + (rb + d + 32) * 2) = packh2(r2[0], r2[1]);
                    }
                }
        } else {
            #pragma unroll
            for (int mt = 0; mt < 2; mt++)
                #pragma unroll
                for (int half = 0; half < 2; half++) {
                    int m = m0 + wm * 32 + mt * 16 + g + half * 8;
                    int b = m >> 11, sq = m & 2047;
                    size_t rb = (((size_t)b * NH + hd) * NS + sq) * NDH;
                    #pragma unroll
                    for (int nt = 0; nt < 8; nt++) {
                        int d = nt * 8 + tig * 2;
                        float vx = acc[mt][nt][half*2]   + bcol[nt][0];
                        float vy = acc[mt][nt][half*2+1] + bcol[nt][1];
                        *(uint32_t*)((char*)g_Vhf + (rb + d) * 2) = packh2(vx, vy);
                    }
                }
        }
    } else {
        #pragma unroll
        for (int mt = 0; mt < 2; mt++)
            #pragma unroll
            for (int half = 0; half < 2; half++) {
                int m = m0 + wm * 32 + mt * 16 + g + half * 8;
                #pragma unroll
                for (int nt = 0; nt < 8; nt++) {
                    int n = nBase + nt * 8 + tig * 2;
                    float2 v;
                    v.x = acc[mt][nt][half*2]   + bcol[nt][0];
                    v.y = acc[mt][nt][half*2+1] + bcol[nt][1];
                    *(float2*)(C + (size_t)m * N + n) = v;
                }
            }
    }
}

// ===========================================================================
// fp16 flash attention: hoisted Q fragments, warp-vote rescale skip,
// 3-stage ring of DOUBLE KV stages (2 x 64-key tiles per stage) ->
// 16 barrier rounds instead of 32. smem 112KB, occ 2.
// ===========================================================================
#define AQ 0
#define ASTG_BASE 16384
#define ASTG 32768                       // 2 tiles: K0|V0|K1|V1 (8KB each)
#define AT_SMEM (ASTG_BASE + 3*ASTG)     // 114688
#define ONESH2 0x3C003C00u               // half2(1.0, 1.0)
#define NT2 (NS/128)                     // 16 double-tile iterations

__global__ __launch_bounds__(128, 2) void attn_f16()
{
    extern __shared__ char sma[];
    const uint32_t sb = smem_u32(sma);

    const int tid = threadIdx.x;
    const int warp = tid >> 5, lane = tid & 31;
    const int qt = blockIdx.x, bh = blockIdx.y;

    const size_t qbase  = ((size_t)bh * NS + qt * 128) * NDH;
    const size_t kvbase = (size_t)bh * NS * NDH;

    // ---- issue Q fill -----------------------------------------------------
    {
        #pragma unroll
        for (int j = 0; j < 8; j++) {
            int idx = tid + j * 128;
            int row = idx >> 3, c = idx & 7;
            cpa16(sb + AQ + swz128(row, c), g_Qhf + qbase + (size_t)row * NDH + c * 8);
        }
        CP_COMMIT();
    }

    // double KV stage: tiles 2*it, 2*it+1
    const int rKV = tid >> 3, cKV = tid & 7;
    auto issue_kv2 = [&](int it) {
        const uint32_t base = sb + ASTG_BASE + (it % 3) * ASTG;
        #pragma unroll
        for (int sub = 0; sub < 2; sub++) {
            const uint32_t tb = base + sub * 16384;
            const int kt = it * 2 + sub;
            #pragma unroll
            for (int j = 0; j < 4; j++) {
                int row = rKV + j * 16;
                uint32_t o = swz128(row, cKV);
                size_t go = kvbase + (size_t)(kt * 64 + row) * NDH + cKV * 8;
                cpa16(tb + o,        g_Khf + go);
                cpa16(tb + 8192 + o, g_Vhf + go);
            }
        }
    };
    issue_kv2(0); CP_COMMIT();
    issue_kv2(1); CP_COMMIT();

    // ---- fragment smem offsets --------------------------------------------
    uint32_t qOff[4][2];
    #pragma unroll
    for (int kc = 0; kc < 4; kc++)
        #pragma unroll
        for (int mt = 0; mt < 2; mt++) {
            int r = warp * 32 + mt * 16 + (lane & 15);
            int c = kc * 2 + ((lane >> 4) & 1);
            qOff[kc][mt] = swz128(r, c);
        }
    uint32_t kOff[4][4];
    #pragma unroll
    for (int kc = 0; kc < 4; kc++)
        #pragma unroll
        for (int ntp = 0; ntp < 4; ntp++) {
            int r = ntp * 16 + (lane & 7) + ((lane >> 4) & 1) * 8;
            int c = kc * 2 + ((lane >> 3) & 1);
            kOff[kc][ntp] = swz128(r, c);
        }
    uint32_t vOff[4][4];
    #pragma unroll
    for (int kq = 0; kq < 4; kq++)
        #pragma unroll
        for (int dp = 0; dp < 4; dp++) {
            int r = kq * 16 + (lane & 7) + ((lane >> 3) & 1) * 8;
            int c = dp * 2 + ((lane >> 4) & 1);
            vOff[kq][dp] = swz128(r, c);
        }

    // ---- wait for Q, hoist Q fragments ------------------------------------
    CP_WAIT(2);
    __syncthreads();
    uint32_t qf[4][2][4];
    #pragma unroll
    for (int kc = 0; kc < 4; kc++) {
        ldmx4(sb + AQ + qOff[kc][0], qf[kc][0]);
        ldmx4(sb + AQ + qOff[kc][1], qf[kc][1]);
    }

    float Oa[2][8][4];
    float lacc[2][4];
    float mrun[2][2];
    #pragma unroll
    for (int mt = 0; mt < 2; mt++) {
        mrun[mt][0] = -INFINITY; mrun[mt][1] = -INFINITY;
        #pragma unroll
        for (int i = 0; i < 4; i++) lacc[mt][i] = 0.f;
        #pragma unroll
        for (int dt = 0; dt < 8; dt++)
            #pragma unroll
            for (int i = 0; i < 4; i++) Oa[mt][dt][i] = 0.f;
    }

    for (int it = 0; it < NT2; it++) {
        if (it + 1 < NT2) { CP_WAIT(1); } else { CP_WAIT(0); }
        __syncthreads();
        if (it + 2 < NT2) { issue_kv2(it + 2); CP_COMMIT(); }

        const uint32_t stage = sb + ASTG_BASE + (it % 3) * ASTG;

        #pragma unroll
        for (int sub = 0; sub < 2; sub++) {
            const uint32_t kb = stage + sub * 16384;

            // ---- S = Q K^T ------------------------------------------------
            float S[2][8][4];
            #pragma unroll
            for (int mt = 0; mt < 2; mt++)
                #pragma unroll
                for (int nt = 0; nt < 8; nt++)
                    #pragma unroll
                    for (int i = 0; i < 4; i++) S[mt][nt][i] = 0.f;

            #pragma unroll
            for (int kc = 0; kc < 4; kc++) {
                #pragma unroll
                for (int ntp = 0; ntp < 4; ntp++) {
                    uint32_t kf[4];
                    ldmx4(kb + kOff[kc][ntp], kf);
                    mma16816(S[0][2*ntp],   qf[kc][0], kf[0], kf[1]);
                    mma16816(S[0][2*ntp+1], qf[kc][0], kf[2], kf[3]);
                    mma16816(S[1][2*ntp],   qf[kc][1], kf[0], kf[1]);
                    mma16816(S[1][2*ntp+1], qf[kc][1], kf[2], kf[3]);
                }
            }

            // ---- softmax: fp32 max -> half2 exp; vote-skip rescale --------
            uint32_t P2[2][8][2];
            #pragma unroll
            for (int mt = 0; mt < 2; mt++) {
                float mx0 = -INFINITY, mx1 = -INFINITY;
                #pragma unroll
                for (int j = 0; j < 8; j++) {
                    mx0 = fmaxf(mx0, fmaxf(S[mt][j][0], S[mt][j][1]));
                    mx1 = fmaxf(mx1, fmaxf(S[mt][j][2], S[mt][j][3]));
                }
                mx0 = fmaxf(mx0, __shfl_xor_sync(0xffffffffu, mx0, 1));
                mx0 = fmaxf(mx0, __shfl_xor_sync(0xffffffffu, mx0, 2));
                mx1 = fmaxf(mx1, __shfl_xor_sync(0xffffffffu, mx1, 1));
                mx1 = fmaxf(mx1, __shfl_xor_sync(0xffffffffu, mx1, 2));
                float nm0 = fmaxf(mrun[mt][0], mx0);
                float nm1 = fmaxf(mrun[mt][1], mx1);
                bool grew = (nm0 > mrun[mt][0]) || (nm1 > mrun[mt][1]);
                if (__any_sync(0xffffffffu, grew)) {
                    float a0 = __expf(mrun[mt][0] - nm0);
                    float a1 = __expf(mrun[mt][1] - nm1);
                    #pragma unroll
                    for (int dt = 0; dt < 8; dt++) {
                        Oa[mt][dt][0] *= a0; Oa[mt][dt][1] *= a0;
                        Oa[mt][dt][2] *= a1; Oa[mt][dt][3] *= a1;
                    }
                    lacc[mt][0] *= a0; lacc[mt][1] *= a0;
                    lacc[mt][2] *= a1; lacc[mt][3] *= a1;
                }
                mrun[mt][0] = nm0; mrun[mt][1] = nm1;
                float nb0 = nm0 * LOG2E, nb1 = nm1 * LOG2E;
                #pragma unroll
                for (int j = 0; j < 8; j++) {
                    float t0 = fmaf(S[mt][j][0], LOG2E, -nb0);
                    float t1 = fmaf(S[mt][j][1], LOG2E, -nb0);
                    P2[mt][j][0] = ex2h2(packh2(t0, t1));
                    float t2 = fmaf(S[mt][j][2], LOG2E, -nb1);
                    float t3 = fmaf(S[mt][j][3], LOG2E, -nb1);
                    P2[mt][j][1] = ex2h2(packh2(t2, t3));
                }
            }

            // ---- O += P V ; l += P @ ones ---------------------------------
            #pragma unroll
            for (int kq = 0; kq < 4; kq++) {
                uint32_t pa0[4] = {P2[0][2*kq][0], P2[0][2*kq][1],
                                   P2[0][2*kq+1][0], P2[0][2*kq+1][1]};
                uint32_t pa1[4] = {P2[1][2*kq][0], P2[1][2*kq][1],
                                   P2[1][2*kq+1][0], P2[1][2*kq+1][1]};
                mma16816(lacc[0], pa0, ONESH2, ONESH2);
                mma16816(lacc[1], pa1, ONESH2, ONESH2);
                #pragma unroll
                for (int dp = 0; dp < 4; dp++) {
                    uint32_t vf[4];
                    ldmx4t(kb + 8192 + vOff[kq][dp], vf);
                    mma16816(Oa[0][2*dp],   pa0, vf[0], vf[1]);
                    mma16816(Oa[0][2*dp+1], pa0, vf[2], vf[3]);
                    mma16816(Oa[1][2*dp],   pa1, vf[0], vf[1]);
                    mma16816(Oa[1][2*dp+1], pa1, vf[2], vf[3]);
                }
            }
        }
    }

    // ---- epilogue: O /= l -> ctx fp16 [B,S,H*Dh] --------------------------
    const int b = bh >> 4, h = bh & 15;
    const int g = lane >> 2, tg = lane & 3;
    #pragma unroll
    for (int mt = 0; mt < 2; mt++)
        #pragma unroll
        for (int half = 0; half < 2; half++) {
            int q = qt * 128 + warp * 32 + mt * 16 + g + half * 8;
            float inv = 1.0f / lacc[mt][half*2];
            size_t rb = ((size_t)b * NS + q) * ND + h * NDH;
            #pragma unroll
            for (int dt = 0; dt < 8; dt++) {
                float vx = Oa[mt][dt][half*2]   * inv;
                float vy = Oa[mt][dt][half*2+1] * inv;
                size_t o = rb + dt * 8 + tg * 2;
                *(uint32_t*)((char*)g_ctxhf + o * 2) = packh2(vx, vy);
            }
        }
}

// ===========================================================================
extern "C" void kernel_launch(void* const* d_in, const int* in_sizes, int n_in,
                              void* d_out, int out_size)
{
    (void)in_sizes; (void)n_in; (void)out_size;
    const float* x      = (const float*)d_in[0];
    const int*   p      = (const int*)d_in[1];
    const float* Wqkv_w = (const float*)d_in[2];
    const float* Wqkv_b = (const float*)d_in[3];
    const float* Wo_w   = (const float*)d_in[4];
    const float* Wo_b   = (const float*)d_in[5];
    float* out = (float*)d_out;

    cudaFuncSetAttribute(gemm_f16<0>,
                         cudaFuncAttributeMaxDynamicSharedMemorySize, GK_SMEM);
    cudaFuncSetAttribute(gemm_f16<1>,
                         cudaFuncAttributeMaxDynamicSharedMemorySize, GK_SMEM);
    cudaFuncSetAttribute(attn_f16,
                         cudaFuncAttributeMaxDynamicSharedMemorySize, AT_SMEM);

    __half *xh, *wqh, *woh, *ctxh;
    cudaGetSymbolAddress((void**)&xh,   g_xhf);
    cudaGetSymbolAddress((void**)&wqh,  g_wqhf);
    cudaGetSymbolAddress((void**)&woh,  g_wohf);
    cudaGetSymbolAddress((void**)&ctxh, g_ctxhf);

    freq_kernel<<<1, 32>>>();

    int n4x = MT * ND / 4, n4wq = 3 * ND * ND / 4, n4wo = ND * ND / 4;
    int n4t = n4x + n4wq + n4wo;
    conv_all<<<(n4t + 255) / 256, 256>>>(
        (const float4*)x, (const float4*)Wqkv_w, (const float4*)Wo_w,
        (uint2*)xh, (uint2*)wqh, (uint2*)woh, n4x, n4wq, n4wo);

    dim3 g1(3 * ND / 128, MT / 128);
    gemm_f16<0><<<g1, 256, GK_SMEM>>>(xh, wqh, Wqkv_b, p, nullptr, 3 * ND, ND);

    attn_f16<<<dim3(NS / 128, NB * NH), 128, AT_SMEM>>>();

    dim3 g2(ND / 128, MT / 128);
    gemm_f16<1><<<g2, 256, GK_SMEM>>>(ctxh, woh, Wo_b, nullptr, out, ND, ND);
}

// round 15
// speedup vs baseline: 1.1043x; 1.0166x over previous
#include <cuda_runtime.h>
#include <cuda_fp16.h>
#include <math.h>
#include <stdint.h>

#define NB   4
#define NS   2048
#define ND   1024
#define NH   16
#define NDH  64
#define MT   (NB*NS)          // 8192 rows
#define QKV_ELEMS ((size_t)NB*NH*NS*NDH)
#define LOG2E 1.4426950408889634f

// ---------------- scratch (device globals: no allocation allowed) ----------
__device__ __half g_Qhf[QKV_ELEMS];           // post-RoPE, *0.125, fp16
__device__ __half g_Khf[QKV_ELEMS];
__device__ __half g_Vhf[QKV_ELEMS];
__device__ __half g_xhf[(size_t)MT*ND];
__device__ __half g_wqhf[(size_t)3*ND*ND];
__device__ __half g_wohf[(size_t)ND*ND];
__device__ __half g_ctxhf[(size_t)MT*ND];
__device__ float  g_freq[32];                 // 10000^(-i/32), fp32 (from double)

// ======================= helpers ===========================================
__device__ __forceinline__ uint32_t smem_u32(const void* p) {
    uint32_t a;
    asm("{ .reg .u64 t; cvta.to.shared.u64 t, %1; cvt.u32.u64 %0, t; }"
        : "=r"(a) : "l"(p));
    return a;
}
__device__ __forceinline__ void ldmx4(uint32_t addr, uint32_t r[4]) {
    asm volatile("ldmatrix.sync.aligned.m8n8.x4.shared.b16 {%0,%1,%2,%3}, [%4];"
                 : "=r"(r[0]), "=r"(r[1]), "=r"(r[2]), "=r"(r[3]) : "r"(addr));
}
__device__ __forceinline__ void ldmx4t(uint32_t addr, uint32_t r[4]) {
    asm volatile("ldmatrix.sync.aligned.m8n8.x4.trans.shared.b16 {%0,%1,%2,%3}, [%4];"
                 : "=r"(r[0]), "=r"(r[1]), "=r"(r[2]), "=r"(r[3]) : "r"(addr));
}
__device__ __forceinline__ void mma16816(float c[4], const uint32_t a[4],
                                         uint32_t b0, uint32_t b1) {
    asm("mma.sync.aligned.m16n8k16.row.col.f32.f16.f16.f32 "
        "{%0,%1,%2,%3}, {%4,%5,%6,%7}, {%8,%9}, {%0,%1,%2,%3};"
        : "+f"(c[0]), "+f"(c[1]), "+f"(c[2]), "+f"(c[3])
        : "r"(a[0]), "r"(a[1]), "r"(a[2]), "r"(a[3]), "r"(b0), "r"(b1));
}
__device__ __forceinline__ uint32_t packh2(float x, float y) {
    __half2 h = __floats2half2_rn(x, y);
    return *(uint32_t*)&h;
}
__device__ __forceinline__ uint32_t ex2h2(uint32_t x) {
    uint32_t d;
    asm("ex2.approx.f16x2 %0, %1;" : "=r"(d) : "r"(x));
    return d;
}
// XOR swizzle for 128B rows: chunk c (0..7)
__device__ __forceinline__ uint32_t swz128(int row, int c) {
    return (uint32_t)(row * 128 + ((c ^ (row & 7)) * 16));
}
__device__ __forceinline__ void cpa16(uint32_t dst, const void* src) {
    asm volatile("cp.async.cg.shared.global [%0], [%1], 16;"
                 :: "r"(dst), "l"(src));
}
#define CP_COMMIT()  asm volatile("cp.async.commit_group;")
#define CP_WAIT(n)   asm volatile("cp.async.wait_group %0;" :: "n"(n))

// ===========================================================================
// merged fp32 -> fp16 converts for x, Wqkv, Wo (+ RoPE freqs in block 0)
// ===========================================================================
__global__ void conv_all(const float4* __restrict__ x,
                         const float4* __restrict__ wq,
                         const float4* __restrict__ wo,
                         uint2* __restrict__ xh, uint2* __restrict__ wqh,
                         uint2* __restrict__ woh,
                         int n4x, int n4wq, int n4wo)
{
    if (blockIdx.x == 0 && threadIdx.x < 32)
        g_freq[threadIdx.x] =
            (float)exp(-(double)threadIdx.x * (9.210340371976184 / 32.0));

    int i = blockIdx.x * blockDim.x + threadIdx.x;
    const float4* src; uint2* dst; int idx;
    if (i < n4x)                 { src = x;  dst = xh;  idx = i; }
    else if (i < n4x + n4wq)     { src = wq; dst = wqh; idx = i - n4x; }
    else if (i < n4x + n4wq + n4wo) { src = wo; dst = woh; idx = i - n4x - n4wq; }
    else return;
    float4 v = src[idx];
    dst[idx] = make_uint2(packh2(v.x, v.y), packh2(v.z, v.w));
}

// ===========================================================================
// fp16 GEMM (unchanged from passing R13/R14): 256 thr / 8 warps, warp tile
// 32x64, K-chunk 64 per stage (128B rows), 3-stage cp.async ring, occ 2.
// EPI==0: fused QKV epilogue — RoPE(Q,K) -> fp16 (Q *0.125), V -> fp16.
// EPI==1: fp32 C.
// ===========================================================================
#define GSTG 32768
#define GK_SMEM (3*GSTG)     // 98304

template<int EPI>
__global__ __launch_bounds__(256, 2) void gemm_f16(
    const __half* __restrict__ A, const __half* __restrict__ W,
    const float* __restrict__ bias, const int* __restrict__ posp,
    float* __restrict__ C, int N, int K)
{
    extern __shared__ char smc[];
    const uint32_t sb = smem_u32(smc);

    const int tid  = threadIdx.x;
    const int warp = tid >> 5, lane = tid & 31;
    const int wm = warp & 3, cg = warp >> 2;
    const int m0 = blockIdx.y * 128, n0 = blockIdx.x * 128;

    uint32_t offs[4];
    const __half* pA[4];
    const __half* pW[4];
    #pragma unroll
    for (int j = 0; j < 4; j++) {
        int idx = tid + j * 256;
        int row = idx >> 3, c = idx & 7;
        offs[j] = swz128(row, c);
        pA[j] = A + (size_t)(m0 + row) * K + c * 8;
        pW[j] = W + (size_t)(n0 + row) * K + c * 8;
    }

    float acc[2][8][4];
    #pragma unroll
    for (int mt = 0; mt < 2; mt++)
        #pragma unroll
        for (int nt = 0; nt < 8; nt++)
            #pragma unroll
            for (int i = 0; i < 4; i++) acc[mt][nt][i] = 0.f;

    uint32_t aOff[4][2], bOff[4][4];
    #pragma unroll
    for (int kc = 0; kc < 4; kc++) {
        #pragma unroll
        for (int mt = 0; mt < 2; mt++) {
            int r = wm * 32 + mt * 16 + (lane & 15);
            int c = kc * 2 + ((lane >> 4) & 1);
            aOff[kc][mt] = swz128(r, c);
        }
        #pragma unroll
        for (int ntp = 0; ntp < 4; ntp++) {
            int r = cg * 64 + ntp * 16 + (lane & 7) + ((lane >> 4) & 1) * 8;
            int c = kc * 2 + ((lane >> 3) & 1);
            bOff[kc][ntp] = swz128(r, c);
        }
    }

    const int NSTG = K / 64;

    auto issue = [&](int s) {
        const uint32_t base = sb + (s % 3) * GSTG;
        const int k0 = s * 64;
        #pragma unroll
        for (int j = 0; j < 4; j++) {
            cpa16(base + offs[j],         pA[j] + k0);
            cpa16(base + 16384 + offs[j], pW[j] + k0);
        }
    };

    issue(0); CP_COMMIT();
    issue(1); CP_COMMIT();

    for (int s = 0; s < NSTG; s++) {
        if (s + 1 < NSTG) { CP_WAIT(1); } else { CP_WAIT(0); }
        __syncthreads();
        if (s + 2 < NSTG) { issue(s + 2); CP_COMMIT(); }

        const uint32_t base = sb + (s % 3) * GSTG;
        #pragma unroll
        for (int kc = 0; kc < 4; kc++) {
            uint32_t a0[4], a1[4];
            ldmx4(base + aOff[kc][0], a0);
            ldmx4(base + aOff[kc][1], a1);
            #pragma unroll
            for (int ntp = 0; ntp < 4; ntp++) {
                uint32_t bfr[4];
                ldmx4(base + 16384 + bOff[kc][ntp], bfr);
                mma16816(acc[0][2*ntp],   a0, bfr[0], bfr[1]);
                mma16816(acc[0][2*ntp+1], a0, bfr[2], bfr[3]);
                mma16816(acc[1][2*ntp],   a1, bfr[0], bfr[1]);
                mma16816(acc[1][2*ntp+1], a1, bfr[2], bfr[3]);
            }
        }
    }

    // ---------------- epilogue ---------------------------------------------
    const int g = lane >> 2, tig = lane & 3;
    const int nBase = n0 + cg * 64;

    float bcol[8][2];
    #pragma unroll
    for (int nt = 0; nt < 8; nt++) {
        bcol[nt][0] = bias[nBase + nt * 8 + tig * 2];
        bcol[nt][1] = bias[nBase + nt * 8 + tig * 2 + 1];
    }

    if (EPI == 0) {
        int part = nBase >> 10;
        int hd   = (nBase & 1023) >> 6;
        if (part < 2) {
            __half* dst = part ? g_Khf : g_Qhf;
            const float sc = part ? 1.0f : 0.125f;
            float fr[4][2];
            #pragma unroll
            for (int nt = 0; nt < 4; nt++) {
                fr[nt][0] = g_freq[nt * 8 + tig * 2];
                fr[nt][1] = g_freq[nt * 8 + tig * 2 + 1];
            }
            #pragma unroll
            for (int mt = 0; mt < 2; mt++)
                #pragma unroll
                for (int half = 0; half < 2; half++) {
                    int m = m0 + wm * 32 + mt * 16 + g + half * 8;
                    int b = m >> 11, sq = m & 2047;
                    size_t rb = (((size_t)b * NH + hd) * NS + sq) * NDH;
                    float pos = (float)posp[b * NS + sq];
                    #pragma unroll
                    for (int nt = 0; nt < 4; nt++) {
                        float r1[2], r2[2];
                        #pragma unroll
                        for (int k = 0; k < 2; k++) {
                            float ang = pos * fr[nt][k];
                            float c, sn;
                            sincosf(ang, &sn, &c);
                            float q1 = acc[mt][nt][half*2 + k]   + bcol[nt][k];
                            float q2 = acc[mt][nt+4][half*2 + k] + bcol[nt+4][k];
                            r1[k] = (q1 * c + q2 * sn) * sc;
                            r2[k] = (q2 * c - q1 * sn) * sc;
                        }
                        int d = nt * 8 + tig * 2;
                        *(uint32_t*)((char*)dst + (rb + d) * 2)      = packh2(r1[0], r1[1]);
                        *(uint32_t*)((char*)dst + (rb + d + 32) * 2) = packh2(r2[0], r2[1]);
                    }
                }
        } else {
            #pragma unroll
            for (int mt = 0; mt < 2; mt++)
                #pragma unroll
                for (int half = 0; half < 2; half++) {
                    int m = m0 + wm * 32 + mt * 16 + g + half * 8;
                    int b = m >> 11, sq = m & 2047;
                    size_t rb = (((size_t)b * NH + hd) * NS + sq) * NDH;
                    #pragma unroll
                    for (int nt = 0; nt < 8; nt++) {
                        int d = nt * 8 + tig * 2;
                        float vx = acc[mt][nt][half*2]   + bcol[nt][0];
                        float vy = acc[mt][nt][half*2+1] + bcol[nt][1];
                        *(uint32_t*)((char*)g_Vhf + (rb + d) * 2) = packh2(vx, vy);
                    }
                }
        }
    } else {
        #pragma unroll
        for (int mt = 0; mt < 2; mt++)
            #pragma unroll
            for (int half = 0; half < 2; half++) {
                int m = m0 + wm * 32 + mt * 16 + g + half * 8;
                #pragma unroll
                for (int nt = 0; nt < 8; nt++) {
                    int n = nBase + nt * 8 + tig * 2;
                    float2 v;
                    v.x = acc[mt][nt][half*2]   + bcol[nt][0];
                    v.y = acc[mt][nt][half*2+1] + bcol[nt][1];
                    *(float2*)(C + (size_t)m * N + n) = v;
                }
            }
    }
}

// ===========================================================================
// fp16 flash attention: hoisted Q fragments, warp-vote rescale skip,
// 3-stage ring of double KV stages (R14), ILP-interleaved softmax chains.
// ===========================================================================
#define AQ 0
#define ASTG_BASE 16384
#define ASTG 32768                       // 2 tiles: K0|V0|K1|V1 (8KB each)
#define AT_SMEM (ASTG_BASE + 3*ASTG)     // 114688
#define ONESH2 0x3C003C00u               // half2(1.0, 1.0)
#define NT2 (NS/128)                     // 16 double-tile iterations

__global__ __launch_bounds__(128, 2) void attn_f16()
{
    extern __shared__ char sma[];
    const uint32_t sb = smem_u32(sma);

    const int tid = threadIdx.x;
    const int warp = tid >> 5, lane = tid & 31;
    const int qt = blockIdx.x, bh = blockIdx.y;

    const size_t qbase  = ((size_t)bh * NS + qt * 128) * NDH;
    const size_t kvbase = (size_t)bh * NS * NDH;

    // ---- issue Q fill -----------------------------------------------------
    {
        #pragma unroll
        for (int j = 0; j < 8; j++) {
            int idx = tid + j * 128;
            int row = idx >> 3, c = idx & 7;
            cpa16(sb + AQ + swz128(row, c), g_Qhf + qbase + (size_t)row * NDH + c * 8);
        }
        CP_COMMIT();
    }

    // double KV stage: tiles 2*it, 2*it+1
    const int rKV = tid >> 3, cKV = tid & 7;
    auto issue_kv2 = [&](int it) {
        const uint32_t base = sb + ASTG_BASE + (it % 3) * ASTG;
        #pragma unroll
        for (int sub = 0; sub < 2; sub++) {
            const uint32_t tb = base + sub * 16384;
            const int kt = it * 2 + sub;
            #pragma unroll
            for (int j = 0; j < 4; j++) {
                int row = rKV + j * 16;
                uint32_t o = swz128(row, cKV);
                size_t go = kvbase + (size_t)(kt * 64 + row) * NDH + cKV * 8;
                cpa16(tb + o,        g_Khf + go);
                cpa16(tb + 8192 + o, g_Vhf + go);
            }
        }
    };
    issue_kv2(0); CP_COMMIT();
    issue_kv2(1); CP_COMMIT();

    // ---- fragment smem offsets --------------------------------------------
    uint32_t qOff[4][2];
    #pragma unroll
    for (int kc = 0; kc < 4; kc++)
        #pragma unroll
        for (int mt = 0; mt < 2; mt++) {
            int r = warp * 32 + mt * 16 + (lane & 15);
            int c = kc * 2 + ((lane >> 4) & 1);
            qOff[kc][mt] = swz128(r, c);
        }
    uint32_t kOff[4][4];
    #pragma unroll
    for (int kc = 0; kc < 4; kc++)
        #pragma unroll
        for (int ntp = 0; ntp < 4; ntp++) {
            int r = ntp * 16 + (lane & 7) + ((lane >> 4) & 1) * 8;
            int c = kc * 2 + ((lane >> 3) & 1);
            kOff[kc][ntp] = swz128(r, c);
        }
    uint32_t vOff[4][4];
    #pragma unroll
    for (int kq = 0; kq < 4; kq++)
        #pragma unroll
        for (int dp = 0; dp < 4; dp++) {
            int r = kq * 16 + (lane & 7) + ((lane >> 3) & 1) * 8;
            int c = dp * 2 + ((lane >> 4) & 1);
            vOff[kq][dp] = swz128(r, c);
        }

    // ---- wait for Q, hoist Q fragments ------------------------------------
    CP_WAIT(2);
    __syncthreads();
    uint32_t qf[4][2][4];
    #pragma unroll
    for (int kc = 0; kc < 4; kc++) {
        ldmx4(sb + AQ + qOff[kc][0], qf[kc][0]);
        ldmx4(sb + AQ + qOff[kc][1], qf[kc][1]);
    }

    float Oa[2][8][4];
    float lacc[2][4];
    float mrun[2][2];
    #pragma unroll
    for (int mt = 0; mt < 2; mt++) {
        mrun[mt][0] = -INFINITY; mrun[mt][1] = -INFINITY;
        #pragma unroll
        for (int i = 0; i < 4; i++) lacc[mt][i] = 0.f;
        #pragma unroll
        for (int dt = 0; dt < 8; dt++)
            #pragma unroll
            for (int i = 0; i < 4; i++) Oa[mt][dt][i] = 0.f;
    }

    for (int it = 0; it < NT2; it++) {
        if (it + 1 < NT2) { CP_WAIT(1); } else { CP_WAIT(0); }
        __syncthreads();
        if (it + 2 < NT2) { issue_kv2(it + 2); CP_COMMIT(); }

        const uint32_t stage = sb + ASTG_BASE + (it % 3) * ASTG;

        #pragma unroll
        for (int sub = 0; sub < 2; sub++) {
            const uint32_t kb = stage + sub * 16384;

            // ---- S = Q K^T ------------------------------------------------
            float S[2][8][4];
            #pragma unroll
            for (int mt = 0; mt < 2; mt++)
                #pragma unroll
                for (int nt = 0; nt < 8; nt++)
                    #pragma unroll
                    for (int i = 0; i < 4; i++) S[mt][nt][i] = 0.f;

            #pragma unroll
            for (int kc = 0; kc < 4; kc++) {
                #pragma unroll
                for (int ntp = 0; ntp < 4; ntp++) {
                    uint32_t kf[4];
                    ldmx4(kb + kOff[kc][ntp], kf);
                    mma16816(S[0][2*ntp],   qf[kc][0], kf[0], kf[1]);
                    mma16816(S[0][2*ntp+1], qf[kc][0], kf[2], kf[3]);
                    mma16816(S[1][2*ntp],   qf[kc][1], kf[0], kf[1]);
                    mma16816(S[1][2*ntp+1], qf[kc][1], kf[2], kf[3]);
                }
            }

            // ---- softmax: ILP-interleaved across mt; merged rescale vote --
            float mx[2][2];
            #pragma unroll
            for (int mt = 0; mt < 2; mt++) {
                float m0v = -INFINITY, m1v = -INFINITY;
                #pragma unroll
                for (int j = 0; j < 8; j++) {
                    m0v = fmaxf(m0v, fmaxf(S[mt][j][0], S[mt][j][1]));
                    m1v = fmaxf(m1v, fmaxf(S[mt][j][2], S[mt][j][3]));
                }
                mx[mt][0] = m0v; mx[mt][1] = m1v;
            }
            // four independent shuffle chains, issued back-to-back
            #pragma unroll
            for (int mt = 0; mt < 2; mt++) {
                mx[mt][0] = fmaxf(mx[mt][0], __shfl_xor_sync(0xffffffffu, mx[mt][0], 1));
                mx[mt][1] = fmaxf(mx[mt][1], __shfl_xor_sync(0xffffffffu, mx[mt][1], 1));
            }
            #pragma unroll
            for (int mt = 0; mt < 2; mt++) {
                mx[mt][0] = fmaxf(mx[mt][0], __shfl_xor_sync(0xffffffffu, mx[mt][0], 2));
                mx[mt][1] = fmaxf(mx[mt][1], __shfl_xor_sync(0xffffffffu, mx[mt][1], 2));
            }
            float nm[2][2];
            nm[0][0] = fmaxf(mrun[0][0], mx[0][0]);
            nm[0][1] = fmaxf(mrun[0][1], mx[0][1]);
            nm[1][0] = fmaxf(mrun[1][0], mx[1][0]);
            nm[1][1] = fmaxf(mrun[1][1], mx[1][1]);
            bool grew = (nm[0][0] > mrun[0][0]) || (nm[0][1] > mrun[0][1])
                     || (nm[1][0] > mrun[1][0]) || (nm[1][1] > mrun[1][1]);
            if (__any_sync(0xffffffffu, grew)) {
                // per-half alphas; non-growing halves get expf(0)=1 exactly
                float a00 = __expf(mrun[0][0] - nm[0][0]);
                float a01 = __expf(mrun[0][1] - nm[0][1]);
                float a10 = __expf(mrun[1][0] - nm[1][0]);
                float a11 = __expf(mrun[1][1] - nm[1][1]);
                #pragma unroll
                for (int dt = 0; dt < 8; dt++) {
                    Oa[0][dt][0] *= a00; Oa[0][dt][1] *= a00;
                    Oa[0][dt][2] *= a01; Oa[0][dt][3] *= a01;
                    Oa[1][dt][0] *= a10; Oa[1][dt][1] *= a10;
                    Oa[1][dt][2] *= a11; Oa[1][dt][3] *= a11;
                }
                lacc[0][0] *= a00; lacc[0][1] *= a00;
                lacc[0][2] *= a01; lacc[0][3] *= a01;
                lacc[1][0] *= a10; lacc[1][1] *= a10;
                lacc[1][2] *= a11; lacc[1][3] *= a11;
            }
            mrun[0][0] = nm[0][0]; mrun[0][1] = nm[0][1];
            mrun[1][0] = nm[1][0]; mrun[1][1] = nm[1][1];

            uint32_t P2[2][8][2];
            #pragma unroll
            for (int mt = 0; mt < 2; mt++) {
                float nb0 = nm[mt][0] * LOG2E, nb1 = nm[mt][1] * LOG2E;
                #pragma unroll
                for (int j = 0; j < 8; j++) {
                    float t0 = fmaf(S[mt][j][0], LOG2E, -nb0);
                    float t1 = fmaf(S[mt][j][1], LOG2E, -nb0);
                    P2[mt][j][0] = ex2h2(packh2(t0, t1));
                    float t2 = fmaf(S[mt][j][2], LOG2E, -nb1);
                    float t3 = fmaf(S[mt][j][3], LOG2E, -nb1);
                    P2[mt][j][1] = ex2h2(packh2(t2, t3));
                }
            }

            // ---- O += P V ; l += P @ ones ---------------------------------
            #pragma unroll
            for (int kq = 0; kq < 4; kq++) {
                uint32_t pa0[4] = {P2[0][2*kq][0], P2[0][2*kq][1],
                                   P2[0][2*kq+1][0], P2[0][2*kq+1][1]};
                uint32_t pa1[4] = {P2[1][2*kq][0], P2[1][2*kq][1],
                                   P2[1][2*kq+1][0], P2[1][2*kq+1][1]};
                mma16816(lacc[0], pa0, ONESH2, ONESH2);
                mma16816(lacc[1], pa1, ONESH2, ONESH2);
                #pragma unroll
                for (int dp = 0; dp < 4; dp++) {
                    uint32_t vf[4];
                    ldmx4t(kb + 8192 + vOff[kq][dp], vf);
                    mma16816(Oa[0][2*dp],   pa0, vf[0], vf[1]);
                    mma16816(Oa[0][2*dp+1], pa0, vf[2], vf[3]);
                    mma16816(Oa[1][2*dp],   pa1, vf[0], vf[1]);
                    mma16816(Oa[1][2*dp+1], pa1, vf[2], vf[3]);
                }
            }
        }
    }

    // ---- epilogue: O /= l -> ctx fp16 [B,S,H*Dh] --------------------------
    const int b = bh >> 4, h = bh & 15;
    const int g = lane >> 2, tg = lane & 3;
    #pragma unroll
    for (int mt = 0; mt < 2; mt++)
        #pragma unroll
        for (int half = 0; half < 2; half++) {
            int q = qt * 128 + warp * 32 + mt * 16 + g + half * 8;
            float inv = 1.0f / lacc[mt][half*2];
            size_t rb = ((size_t)b * NS + q) * ND + h * NDH;
            #pragma unroll
            for (int dt = 0; dt < 8; dt++) {
                float vx = Oa[mt][dt][half*2]   * inv;
                float vy = Oa[mt][dt][half*2+1] * inv;
                size_t o = rb + dt * 8 + tg * 2;
                *(uint32_t*)((char*)g_ctxhf + o * 2) = packh2(vx, vy);
            }
        }
}

// ===========================================================================
extern "C" void kernel_launch(void* const* d_in, const int* in_sizes, int n_in,
                              void* d_out, int out_size)
{
    (void)in_sizes; (void)n_in; (void)out_size;
    const float* x      = (const float*)d_in[0];
    const int*   p      = (const int*)d_in[1];
    const float* Wqkv_w = (const float*)d_in[2];
    const float* Wqkv_b = (const float*)d_in[3];
    const float* Wo_w   = (const float*)d_in[4];
    const float* Wo_b   = (const float*)d_in[5];
    float* out = (float*)d_out;

    cudaFuncSetAttribute(gemm_f16<0>,
                         cudaFuncAttributeMaxDynamicSharedMemorySize, GK_SMEM);
    cudaFuncSetAttribute(gemm_f16<1>,
                         cudaFuncAttributeMaxDynamicSharedMemorySize, GK_SMEM);
    cudaFuncSetAttribute(attn_f16,
                         cudaFuncAttributeMaxDynamicSharedMemorySize, AT_SMEM);

    __half *xh, *wqh, *woh, *ctxh;
    cudaGetSymbolAddress((void**)&xh,   g_xhf);
    cudaGetSymbolAddress((void**)&wqh,  g_wqhf);
    cudaGetSymbolAddress((void**)&woh,  g_wohf);
    cudaGetSymbolAddress((void**)&ctxh, g_ctxhf);

    int n4x = MT * ND / 4, n4wq = 3 * ND * ND / 4, n4wo = ND * ND / 4;
    int n4t = n4x + n4wq + n4wo;
    conv_all<<<(n4t + 255) / 256, 256>>>(
        (const float4*)x, (const float4*)Wqkv_w, (const float4*)Wo_w,
        (uint2*)xh, (uint2*)wqh, (uint2*)woh, n4x, n4wq, n4wo);

    dim3 g1(3 * ND / 128, MT / 128);
    gemm_f16<0><<<g1, 256, GK_SMEM>>>(xh, wqh, Wqkv_b, p, nullptr, 3 * ND, ND);

    attn_f16<<<dim3(NS / 128, NB * NH), 128, AT_SMEM>>>();

    dim3 g2(ND / 128, MT / 128);
    gemm_f16<1><<<g2, 256, GK_SMEM>>>(ctxh, woh, Wo_b, nullptr, out, ND, ND);
}

// round 16
// speedup vs baseline: 1.1422x; 1.0344x over previous
#include <cuda_runtime.h>
#include <cuda_fp16.h>
#include <math.h>
#include <stdint.h>

#define NB   4
#define NS   2048
#define ND   1024
#define NH   16
#define NDH  64
#define MT   (NB*NS)          // 8192 rows
#define QKV_ELEMS ((size_t)NB*NH*NS*NDH)
#define LOG2E 1.4426950408889634f

// ---------------- scratch (device globals: no allocation allowed) ----------
__device__ __half g_Qhf[QKV_ELEMS];           // post-RoPE, *0.125, fp16
__device__ __half g_Khf[QKV_ELEMS];
__device__ __half g_Vhf[QKV_ELEMS];
__device__ __half g_xhf[(size_t)MT*ND];
__device__ __half g_wqhf[(size_t)3*ND*ND];
__device__ __half g_wohf[(size_t)ND*ND];
__device__ __half g_ctxhf[(size_t)MT*ND];
__device__ float  g_freq[32];                 // 10000^(-i/32), fp32 (from double)

// ======================= helpers ===========================================
__device__ __forceinline__ uint32_t smem_u32(const void* p) {
    uint32_t a;
    asm("{ .reg .u64 t; cvta.to.shared.u64 t, %1; cvt.u32.u64 %0, t; }"
        : "=r"(a) : "l"(p));
    return a;
}
__device__ __forceinline__ void ldmx4(uint32_t addr, uint32_t r[4]) {
    asm volatile("ldmatrix.sync.aligned.m8n8.x4.shared.b16 {%0,%1,%2,%3}, [%4];"
                 : "=r"(r[0]), "=r"(r[1]), "=r"(r[2]), "=r"(r[3]) : "r"(addr));
}
__device__ __forceinline__ void ldmx4t(uint32_t addr, uint32_t r[4]) {
    asm volatile("ldmatrix.sync.aligned.m8n8.x4.trans.shared.b16 {%0,%1,%2,%3}, [%4];"
                 : "=r"(r[0]), "=r"(r[1]), "=r"(r[2]), "=r"(r[3]) : "r"(addr));
}
__device__ __forceinline__ void mma16816(float c[4], const uint32_t a[4],
                                         uint32_t b0, uint32_t b1) {
    asm("mma.sync.aligned.m16n8k16.row.col.f32.f16.f16.f32 "
        "{%0,%1,%2,%3}, {%4,%5,%6,%7}, {%8,%9}, {%0,%1,%2,%3};"
        : "+f"(c[0]), "+f"(c[1]), "+f"(c[2]), "+f"(c[3])
        : "r"(a[0]), "r"(a[1]), "r"(a[2]), "r"(a[3]), "r"(b0), "r"(b1));
}
__device__ __forceinline__ uint32_t packh2(float x, float y) {
    __half2 h = __floats2half2_rn(x, y);
    return *(uint32_t*)&h;
}
__device__ __forceinline__ uint32_t ex2h2(uint32_t x) {
    uint32_t d;
    asm("ex2.approx.f16x2 %0, %1;" : "=r"(d) : "r"(x));
    return d;
}
// XOR swizzle for 128B rows: chunk c (0..7)
__device__ __forceinline__ uint32_t swz128(int row, int c) {
    return (uint32_t)(row * 128 + ((c ^ (row & 7)) * 16));
}
__device__ __forceinline__ void cpa16(uint32_t dst, const void* src) {
    asm volatile("cp.async.cg.shared.global [%0], [%1], 16;"
                 :: "r"(dst), "l"(src));
}
#define CP_COMMIT()  asm volatile("cp.async.commit_group;")
#define CP_WAIT(n)   asm volatile("cp.async.wait_group %0;" :: "n"(n))

// ===========================================================================
// merged fp32 -> fp16 converts for x, Wqkv, Wo (+ RoPE freqs in block 0)
// ===========================================================================
__global__ void conv_all(const float4* __restrict__ x,
                         const float4* __restrict__ wq,
                         const float4* __restrict__ wo,
                         uint2* __restrict__ xh, uint2* __restrict__ wqh,
                         uint2* __restrict__ woh,
                         int n4x, int n4wq, int n4wo)
{
    if (blockIdx.x == 0 && threadIdx.x < 32)
        g_freq[threadIdx.x] =
            (float)exp(-(double)threadIdx.x * (9.210340371976184 / 32.0));

    int i = blockIdx.x * blockDim.x + threadIdx.x;
    const float4* src; uint2* dst; int idx;
    if (i < n4x)                 { src = x;  dst = xh;  idx = i; }
    else if (i < n4x + n4wq)     { src = wq; dst = wqh; idx = i - n4x; }
    else if (i < n4x + n4wq + n4wo) { src = wo; dst = woh; idx = i - n4x - n4wq; }
    else return;
    float4 v = src[idx];
    dst[idx] = make_uint2(packh2(v.x, v.y), packh2(v.z, v.w));
}

// ===========================================================================
// fp16 GEMM (R13/R14 proven): 256 thr / 8 warps, warp tile 32x64, K-chunk 64
// per stage (128B rows), 3-stage cp.async ring, occ 2. m_off for row-split.
// EPI==0: fused QKV epilogue — RoPE(Q,K) -> fp16 (Q *0.125), V -> fp16.
// EPI==1: fp32 C.
// ===========================================================================
#define GSTG 32768
#define GK_SMEM (3*GSTG)     // 98304

template<int EPI>
__global__ __launch_bounds__(256, 2) void gemm_f16(
    const __half* __restrict__ A, const __half* __restrict__ W,
    const float* __restrict__ bias, const int* __restrict__ posp,
    float* __restrict__ C, int N, int K, int m_off)
{
    extern __shared__ char smc[];
    const uint32_t sb = smem_u32(smc);

    const int tid  = threadIdx.x;
    const int warp = tid >> 5, lane = tid & 31;
    const int wm = warp & 3, cg = warp >> 2;
    const int m0 = blockIdx.y * 128 + m_off, n0 = blockIdx.x * 128;

    uint32_t offs[4];
    const __half* pA[4];
    const __half* pW[4];
    #pragma unroll
    for (int j = 0; j < 4; j++) {
        int idx = tid + j * 256;
        int row = idx >> 3, c = idx & 7;
        offs[j] = swz128(row, c);
        pA[j] = A + (size_t)(m0 + row) * K + c * 8;
        pW[j] = W + (size_t)(n0 + row) * K + c * 8;
    }

    float acc[2][8][4];
    #pragma unroll
    for (int mt = 0; mt < 2; mt++)
        #pragma unroll
        for (int nt = 0; nt < 8; nt++)
            #pragma unroll
            for (int i = 0; i < 4; i++) acc[mt][nt][i] = 0.f;

    uint32_t aOff[4][2], bOff[4][4];
    #pragma unroll
    for (int kc = 0; kc < 4; kc++) {
        #pragma unroll
        for (int mt = 0; mt < 2; mt++) {
            int r = wm * 32 + mt * 16 + (lane & 15);
            int c = kc * 2 + ((lane >> 4) & 1);
            aOff[kc][mt] = swz128(r, c);
        }
        #pragma unroll
        for (int ntp = 0; ntp < 4; ntp++) {
            int r = cg * 64 + ntp * 16 + (lane & 7) + ((lane >> 4) & 1) * 8;
            int c = kc * 2 + ((lane >> 3) & 1);
            bOff[kc][ntp] = swz128(r, c);
        }
    }

    const int NSTG = K / 64;

    auto issue = [&](int s) {
        const uint32_t base = sb + (s % 3) * GSTG;
        const int k0 = s * 64;
        #pragma unroll
        for (int j = 0; j < 4; j++) {
            cpa16(base + offs[j],         pA[j] + k0);
            cpa16(base + 16384 + offs[j], pW[j] + k0);
        }
    };

    issue(0); CP_COMMIT();
    issue(1); CP_COMMIT();

    for (int s = 0; s < NSTG; s++) {
        if (s + 1 < NSTG) { CP_WAIT(1); } else { CP_WAIT(0); }
        __syncthreads();
        if (s + 2 < NSTG) { issue(s + 2); CP_COMMIT(); }

        const uint32_t base = sb + (s % 3) * GSTG;
        #pragma unroll
        for (int kc = 0; kc < 4; kc++) {
            uint32_t a0[4], a1[4];
            ldmx4(base + aOff[kc][0], a0);
            ldmx4(base + aOff[kc][1], a1);
            #pragma unroll
            for (int ntp = 0; ntp < 4; ntp++) {
                uint32_t bfr[4];
                ldmx4(base + 16384 + bOff[kc][ntp], bfr);
                mma16816(acc[0][2*ntp],   a0, bfr[0], bfr[1]);
                mma16816(acc[0][2*ntp+1], a0, bfr[2], bfr[3]);
                mma16816(acc[1][2*ntp],   a1, bfr[0], bfr[1]);
                mma16816(acc[1][2*ntp+1], a1, bfr[2], bfr[3]);
            }
        }
    }

    // ---------------- epilogue ---------------------------------------------
    const int g = lane >> 2, tig = lane & 3;
    const int nBase = n0 + cg * 64;

    float bcol[8][2];
    #pragma unroll
    for (int nt = 0; nt < 8; nt++) {
        bcol[nt][0] = bias[nBase + nt * 8 + tig * 2];
        bcol[nt][1] = bias[nBase + nt * 8 + tig * 2 + 1];
    }

    if (EPI == 0) {
        int part = nBase >> 10;
        int hd   = (nBase & 1023) >> 6;
        if (part < 2) {
            __half* dst = part ? g_Khf : g_Qhf;
            const float sc = part ? 1.0f : 0.125f;
            float fr[4][2];
            #pragma unroll
            for (int nt = 0; nt < 4; nt++) {
                fr[nt][0] = g_freq[nt * 8 + tig * 2];
                fr[nt][1] = g_freq[nt * 8 + tig * 2 + 1];
            }
            #pragma unroll
            for (int mt = 0; mt < 2; mt++)
                #pragma unroll
                for (int half = 0; half < 2; half++) {
                    int m = m0 + wm * 32 + mt * 16 + g + half * 8;
                    int b = m >> 11, sq = m & 2047;
                    size_t rb = (((size_t)b * NH + hd) * NS + sq) * NDH;
                    float pos = (float)posp[b * NS + sq];
                    #pragma unroll
                    for (int nt = 0; nt < 4; nt++) {
                        float r1[2], r2[2];
                        #pragma unroll
                        for (int k = 0; k < 2; k++) {
                            float ang = pos * fr[nt][k];
                            float c, sn;
                            sincosf(ang, &sn, &c);
                            float q1 = acc[mt][nt][half*2 + k]   + bcol[nt][k];
                            float q2 = acc[mt][nt+4][half*2 + k] + bcol[nt+4][k];
                            r1[k] = (q1 * c + q2 * sn) * sc;
                            r2[k] = (q2 * c - q1 * sn) * sc;
                        }
                        int d = nt * 8 + tig * 2;
                        *(uint32_t*)((char*)dst + (rb + d) * 2)      = packh2(r1[0], r1[1]);
                        *(uint32_t*)((char*)dst + (rb + d + 32) * 2) = packh2(r2[0], r2[1]);
                    }
                }
        } else {
            #pragma unroll
            for (int mt = 0; mt < 2; mt++)
                #pragma unroll
                for (int half = 0; half < 2; half++) {
                    int m = m0 + wm * 32 + mt * 16 + g + half * 8;
                    int b = m >> 11, sq = m & 2047;
                    size_t rb = (((size_t)b * NH + hd) * NS + sq) * NDH;
                    #pragma unroll
                    for (int nt = 0; nt < 8; nt++) {
                        int d = nt * 8 + tig * 2;
                        float vx = acc[mt][nt][half*2]   + bcol[nt][0];
                        float vy = acc[mt][nt][half*2+1] + bcol[nt][1];
                        *(uint32_t*)((char*)g_Vhf + (rb + d) * 2) = packh2(vx, vy);
                    }
                }
        }
    } else {
        #pragma unroll
        for (int mt = 0; mt < 2; mt++)
            #pragma unroll
            for (int half = 0; half < 2; half++) {
                int m = m0 + wm * 32 + mt * 16 + g + half * 8;
                #pragma unroll
                for (int nt = 0; nt < 8; nt++) {
                    int n = nBase + nt * 8 + tig * 2;
                    float2 v;
                    v.x = acc[mt][nt][half*2]   + bcol[nt][0];
                    v.y = acc[mt][nt][half*2+1] + bcol[nt][1];
                    *(float2*)(C + (size_t)m * N + n) = v;
                }
            }
    }
}

// ===========================================================================
// fp16 flash attention (R15 proven): hoisted Q frags, double KV stages,
// ILP-interleaved softmax, vote-skip rescale. bh0 = batch-half offset.
// ===========================================================================
#define AQ 0
#define ASTG_BASE 16384
#define ASTG 32768                       // 2 tiles: K0|V0|K1|V1 (8KB each)
#define AT_SMEM (ASTG_BASE + 3*ASTG)     // 114688
#define ONESH2 0x3C003C00u               // half2(1.0, 1.0)
#define NT2 (NS/128)                     // 16 double-tile iterations

__global__ __launch_bounds__(128, 2) void attn_f16(int bh0)
{
    extern __shared__ char sma[];
    const uint32_t sb = smem_u32(sma);

    const int tid = threadIdx.x;
    const int warp = tid >> 5, lane = tid & 31;
    const int qt = blockIdx.x, bh = blockIdx.y + bh0;

    const size_t qbase  = ((size_t)bh * NS + qt * 128) * NDH;
    const size_t kvbase = (size_t)bh * NS * NDH;

    {
        #pragma unroll
        for (int j = 0; j < 8; j++) {
            int idx = tid + j * 128;
            int row = idx >> 3, c = idx & 7;
            cpa16(sb + AQ + swz128(row, c), g_Qhf + qbase + (size_t)row * NDH + c * 8);
        }
        CP_COMMIT();
    }

    const int rKV = tid >> 3, cKV = tid & 7;
    auto issue_kv2 = [&](int it) {
        const uint32_t base = sb + ASTG_BASE + (it % 3) * ASTG;
        #pragma unroll
        for (int sub = 0; sub < 2; sub++) {
            const uint32_t tb = base + sub * 16384;
            const int kt = it * 2 + sub;
            #pragma unroll
            for (int j = 0; j < 4; j++) {
                int row = rKV + j * 16;
                uint32_t o = swz128(row, cKV);
                size_t go = kvbase + (size_t)(kt * 64 + row) * NDH + cKV * 8;
                cpa16(tb + o,        g_Khf + go);
                cpa16(tb + 8192 + o, g_Vhf + go);
            }
        }
    };
    issue_kv2(0); CP_COMMIT();
    issue_kv2(1); CP_COMMIT();

    uint32_t qOff[4][2];
    #pragma unroll
    for (int kc = 0; kc < 4; kc++)
        #pragma unroll
        for (int mt = 0; mt < 2; mt++) {
            int r = warp * 32 + mt * 16 + (lane & 15);
            int c = kc * 2 + ((lane >> 4) & 1);
            qOff[kc][mt] = swz128(r, c);
        }
    uint32_t kOff[4][4];
    #pragma unroll
    for (int kc = 0; kc < 4; kc++)
        #pragma unroll
        for (int ntp = 0; ntp < 4; ntp++) {
            int r = ntp * 16 + (lane & 7) + ((lane >> 4) & 1) * 8;
            int c = kc * 2 + ((lane >> 3) & 1);
            kOff[kc][ntp] = swz128(r, c);
        }
    uint32_t vOff[4][4];
    #pragma unroll
    for (int kq = 0; kq < 4; kq++)
        #pragma unroll
        for (int dp = 0; dp < 4; dp++) {
            int r = kq * 16 + (lane & 7) + ((lane >> 3) & 1) * 8;
            int c = dp * 2 + ((lane >> 4) & 1);
            vOff[kq][dp] = swz128(r, c);
        }

    CP_WAIT(2);
    __syncthreads();
    uint32_t qf[4][2][4];
    #pragma unroll
    for (int kc = 0; kc < 4; kc++) {
        ldmx4(sb + AQ + qOff[kc][0], qf[kc][0]);
        ldmx4(sb + AQ + qOff[kc][1], qf[kc][1]);
    }

    float Oa[2][8][4];
    float lacc[2][4];
    float mrun[2][2];
    #pragma unroll
    for (int mt = 0; mt < 2; mt++) {
        mrun[mt][0] = -INFINITY; mrun[mt][1] = -INFINITY;
        #pragma unroll
        for (int i = 0; i < 4; i++) lacc[mt][i] = 0.f;
        #pragma unroll
        for (int dt = 0; dt < 8; dt++)
            #pragma unroll
            for (int i = 0; i < 4; i++) Oa[mt][dt][i] = 0.f;
    }

    for (int it = 0; it < NT2; it++) {
        if (it + 1 < NT2) { CP_WAIT(1); } else { CP_WAIT(0); }
        __syncthreads();
        if (it + 2 < NT2) { issue_kv2(it + 2); CP_COMMIT(); }

        const uint32_t stage = sb + ASTG_BASE + (it % 3) * ASTG;

        #pragma unroll
        for (int sub = 0; sub < 2; sub++) {
            const uint32_t kb = stage + sub * 16384;

            float S[2][8][4];
            #pragma unroll
            for (int mt = 0; mt < 2; mt++)
                #pragma unroll
                for (int nt = 0; nt < 8; nt++)
                    #pragma unroll
                    for (int i = 0; i < 4; i++) S[mt][nt][i] = 0.f;

            #pragma unroll
            for (int kc = 0; kc < 4; kc++) {
                #pragma unroll
                for (int ntp = 0; ntp < 4; ntp++) {
                    uint32_t kf[4];
                    ldmx4(kb + kOff[kc][ntp], kf);
                    mma16816(S[0][2*ntp],   qf[kc][0], kf[0], kf[1]);
                    mma16816(S[0][2*ntp+1], qf[kc][0], kf[2], kf[3]);
                    mma16816(S[1][2*ntp],   qf[kc][1], kf[0], kf[1]);
                    mma16816(S[1][2*ntp+1], qf[kc][1], kf[2], kf[3]);
                }
            }

            float mx[2][2];
            #pragma unroll
            for (int mt = 0; mt < 2; mt++) {
                float m0v = -INFINITY, m1v = -INFINITY;
                #pragma unroll
                for (int j = 0; j < 8; j++) {
                    m0v = fmaxf(m0v, fmaxf(S[mt][j][0], S[mt][j][1]));
                    m1v = fmaxf(m1v, fmaxf(S[mt][j][2], S[mt][j][3]));
                }
                mx[mt][0] = m0v; mx[mt][1] = m1v;
            }
            #pragma unroll
            for (int mt = 0; mt < 2; mt++) {
                mx[mt][0] = fmaxf(mx[mt][0], __shfl_xor_sync(0xffffffffu, mx[mt][0], 1));
                mx[mt][1] = fmaxf(mx[mt][1], __shfl_xor_sync(0xffffffffu, mx[mt][1], 1));
            }
            #pragma unroll
            for (int mt = 0; mt < 2; mt++) {
                mx[mt][0] = fmaxf(mx[mt][0], __shfl_xor_sync(0xffffffffu, mx[mt][0], 2));
                mx[mt][1] = fmaxf(mx[mt][1], __shfl_xor_sync(0xffffffffu, mx[mt][1], 2));
            }
            float nm[2][2];
            nm[0][0] = fmaxf(mrun[0][0], mx[0][0]);
            nm[0][1] = fmaxf(mrun[0][1], mx[0][1]);
            nm[1][0] = fmaxf(mrun[1][0], mx[1][0]);
            nm[1][1] = fmaxf(mrun[1][1], mx[1][1]);
            bool grew = (nm[0][0] > mrun[0][0]) || (nm[0][1] > mrun[0][1])
                     || (nm[1][0] > mrun[1][0]) || (nm[1][1] > mrun[1][1]);
            if (__any_sync(0xffffffffu, grew)) {
                float a00 = __expf(mrun[0][0] - nm[0][0]);
                float a01 = __expf(mrun[0][1] - nm[0][1]);
                float a10 = __expf(mrun[1][0] - nm[1][0]);
                float a11 = __expf(mrun[1][1] - nm[1][1]);
                #pragma unroll
                for (int dt = 0; dt < 8; dt++) {
                    Oa[0][dt][0] *= a00; Oa[0][dt][1] *= a00;
                    Oa[0][dt][2] *= a01; Oa[0][dt][3] *= a01;
                    Oa[1][dt][0] *= a10; Oa[1][dt][1] *= a10;
                    Oa[1][dt][2] *= a11; Oa[1][dt][3] *= a11;
                }
                lacc[0][0] *= a00; lacc[0][1] *= a00;
                lacc[0][2] *= a01; lacc[0][3] *= a01;
                lacc[1][0] *= a10; lacc[1][1] *= a10;
                lacc[1][2] *= a11; lacc[1][3] *= a11;
            }
            mrun[0][0] = nm[0][0]; mrun[0][1] = nm[0][1];
            mrun[1][0] = nm[1][0]; mrun[1][1] = nm[1][1];

            uint32_t P2[2][8][2];
            #pragma unroll
            for (int mt = 0; mt < 2; mt++) {
                float nb0 = nm[mt][0] * LOG2E, nb1 = nm[mt][1] * LOG2E;
                #pragma unroll
                for (int j = 0; j < 8; j++) {
                    float t0 = fmaf(S[mt][j][0], LOG2E, -nb0);
                    float t1 = fmaf(S[mt][j][1], LOG2E, -nb0);
                    P2[mt][j][0] = ex2h2(packh2(t0, t1));
                    float t2 = fmaf(S[mt][j][2], LOG2E, -nb1);
                    float t3 = fmaf(S[mt][j][3], LOG2E, -nb1);
                    P2[mt][j][1] = ex2h2(packh2(t2, t3));
                }
            }

            #pragma unroll
            for (int kq = 0; kq < 4; kq++) {
                uint32_t pa0[4] = {P2[0][2*kq][0], P2[0][2*kq][1],
                                   P2[0][2*kq+1][0], P2[0][2*kq+1][1]};
                uint32_t pa1[4] = {P2[1][2*kq][0], P2[1][2*kq][1],
                                   P2[1][2*kq+1][0], P2[1][2*kq+1][1]};
                mma16816(lacc[0], pa0, ONESH2, ONESH2);
                mma16816(lacc[1], pa1, ONESH2, ONESH2);
                #pragma unroll
                for (int dp = 0; dp < 4; dp++) {
                    uint32_t vf[4];
                    ldmx4t(kb + 8192 + vOff[kq][dp], vf);
                    mma16816(Oa[0][2*dp],   pa0, vf[0], vf[1]);
                    mma16816(Oa[0][2*dp+1], pa0, vf[2], vf[3]);
                    mma16816(Oa[1][2*dp],   pa1, vf[0], vf[1]);
                    mma16816(Oa[1][2*dp+1], pa1, vf[2], vf[3]);
                }
            }
        }
    }

    const int b = bh >> 4, h = bh & 15;
    const int g = lane >> 2, tg = lane & 3;
    #pragma unroll
    for (int mt = 0; mt < 2; mt++)
        #pragma unroll
        for (int half = 0; half < 2; half++) {
            int q = qt * 128 + warp * 32 + mt * 16 + g + half * 8;
            float inv = 1.0f / lacc[mt][half*2];
            size_t rb = ((size_t)b * NS + q) * ND + h * NDH;
            #pragma unroll
            for (int dt = 0; dt < 8; dt++) {
                float vx = Oa[mt][dt][half*2]   * inv;
                float vy = Oa[mt][dt][half*2+1] * inv;
                size_t o = rb + dt * 8 + tg * 2;
                *(uint32_t*)((char*)g_ctxhf + o * 2) = packh2(vx, vy);
            }
        }
}

// ===========================================================================
extern "C" void kernel_launch(void* const* d_in, const int* in_sizes, int n_in,
                              void* d_out, int out_size)
{
    (void)in_sizes; (void)n_in; (void)out_size;
    const float* x      = (const float*)d_in[0];
    const int*   p      = (const int*)d_in[1];
    const float* Wqkv_w = (const float*)d_in[2];
    const float* Wqkv_b = (const float*)d_in[3];
    const float* Wo_w   = (const float*)d_in[4];
    const float* Wo_b   = (const float*)d_in[5];
    float* out = (float*)d_out;

    cudaFuncSetAttribute(gemm_f16<0>,
                         cudaFuncAttributeMaxDynamicSharedMemorySize, GK_SMEM);
    cudaFuncSetAttribute(gemm_f16<1>,
                         cudaFuncAttributeMaxDynamicSharedMemorySize, GK_SMEM);
    cudaFuncSetAttribute(attn_f16,
                         cudaFuncAttributeMaxDynamicSharedMemorySize, AT_SMEM);

    __half *xh, *wqh, *woh, *ctxh;
    cudaGetSymbolAddress((void**)&xh,   g_xhf);
    cudaGetSymbolAddress((void**)&wqh,  g_wqhf);
    cudaGetSymbolAddress((void**)&woh,  g_wohf);
    cudaGetSymbolAddress((void**)&ctxh, g_ctxhf);

    // fork-join streams/events (host objects; created+destroyed per call)
    cudaStream_t sA, sB;
    cudaStreamCreateWithFlags(&sA, cudaStreamNonBlocking);
    cudaStreamCreateWithFlags(&sB, cudaStreamNonBlocking);
    cudaEvent_t evG, evA, evB;
    cudaEventCreateWithFlags(&evG, cudaEventDisableTiming);
    cudaEventCreateWithFlags(&evA, cudaEventDisableTiming);
    cudaEventCreateWithFlags(&evB, cudaEventDisableTiming);

    int n4x = MT * ND / 4, n4wq = 3 * ND * ND / 4, n4wo = ND * ND / 4;
    int n4t = n4x + n4wq + n4wo;
    conv_all<<<(n4t + 255) / 256, 256>>>(
        (const float4*)x, (const float4*)Wqkv_w, (const float4*)Wo_w,
        (uint2*)xh, (uint2*)wqh, (uint2*)woh, n4x, n4wq, n4wo);

    dim3 g1(3 * ND / 128, MT / 128);
    gemm_f16<0><<<g1, 256, GK_SMEM>>>(xh, wqh, Wqkv_b, p, nullptr, 3 * ND, ND, 0);

    // fork after QKV
    cudaEventRecord(evG, 0);
    cudaStreamWaitEvent(sA, evG, 0);
    cudaStreamWaitEvent(sB, evG, 0);

    // chain A: batches 0,1 (bh 0..31, ctx rows 0..4095)
    attn_f16<<<dim3(NS / 128, 32), 128, AT_SMEM, sA>>>(0);
    gemm_f16<1><<<dim3(ND / 128, 32), 256, GK_SMEM, sA>>>(
        ctxh, woh, Wo_b, nullptr, out, ND, ND, 0);
    cudaEventRecord(evA, sA);

    // chain B: batches 2,3 (bh 32..63, ctx rows 4096..8191)
    attn_f16<<<dim3(NS / 128, 32), 128, AT_SMEM, sB>>>(32);
    gemm_f16<1><<<dim3(ND / 128, 32), 256, GK_SMEM, sB>>>(
        ctxh, woh, Wo_b, nullptr, out, ND, ND, 4096);
    cudaEventRecord(evB, sB);

    // join
    cudaStreamWaitEvent(0, evA, 0);
    cudaStreamWaitEvent(0, evB, 0);

    cudaEventDestroy(evG);
    cudaEventDestroy(evA);
    cudaEventDestroy(evB);
    cudaStreamDestroy(sA);
    cudaStreamDestroy(sB);
}

// round 17
// speedup vs baseline: 1.1758x; 1.0294x over previous
#include <cuda_runtime.h>
#include <cuda_fp16.h>
#include <math.h>
#include <stdint.h>

#define NB   4
#define NS   2048
#define ND   1024
#define NH   16
#define NDH  64
#define MT   (NB*NS)          // 8192 rows
#define QKV_ELEMS ((size_t)NB*NH*NS*NDH)
#define LOG2E 1.4426950408889634f

// ---------------- scratch (device globals: no allocation allowed) ----------
__device__ __half g_Qhf[QKV_ELEMS];           // post-RoPE, *0.125, fp16
__device__ __half g_Khf[QKV_ELEMS];
__device__ __half g_Vhf[QKV_ELEMS];
__device__ __half g_xhf[(size_t)MT*ND];
__device__ __half g_wqhf[(size_t)3*ND*ND];
__device__ __half g_wohf[(size_t)ND*ND];
__device__ __half g_ctxhf[(size_t)MT*ND];
__device__ float  g_freq[32];                 // 10000^(-i/32), fp32 (from double)

// ======================= helpers ===========================================
__device__ __forceinline__ uint32_t smem_u32(const void* p) {
    uint32_t a;
    asm("{ .reg .u64 t; cvta.to.shared.u64 t, %1; cvt.u32.u64 %0, t; }"
        : "=r"(a) : "l"(p));
    return a;
}
__device__ __forceinline__ void ldmx4(uint32_t addr, uint32_t r[4]) {
    asm volatile("ldmatrix.sync.aligned.m8n8.x4.shared.b16 {%0,%1,%2,%3}, [%4];"
                 : "=r"(r[0]), "=r"(r[1]), "=r"(r[2]), "=r"(r[3]) : "r"(addr));
}
__device__ __forceinline__ void ldmx4t(uint32_t addr, uint32_t r[4]) {
    asm volatile("ldmatrix.sync.aligned.m8n8.x4.trans.shared.b16 {%0,%1,%2,%3}, [%4];"
                 : "=r"(r[0]), "=r"(r[1]), "=r"(r[2]), "=r"(r[3]) : "r"(addr));
}
__device__ __forceinline__ void mma16816(float c[4], const uint32_t a[4],
                                         uint32_t b0, uint32_t b1) {
    asm("mma.sync.aligned.m16n8k16.row.col.f32.f16.f16.f32 "
        "{%0,%1,%2,%3}, {%4,%5,%6,%7}, {%8,%9}, {%0,%1,%2,%3};"
        : "+f"(c[0]), "+f"(c[1]), "+f"(c[2]), "+f"(c[3])
        : "r"(a[0]), "r"(a[1]), "r"(a[2]), "r"(a[3]), "r"(b0), "r"(b1));
}
__device__ __forceinline__ uint32_t packh2(float x, float y) {
    __half2 h = __floats2half2_rn(x, y);
    return *(uint32_t*)&h;
}
__device__ __forceinline__ uint32_t ex2h2(uint32_t x) {
    uint32_t d;
    asm("ex2.approx.f16x2 %0, %1;" : "=r"(d) : "r"(x));
    return d;
}
// XOR swizzle for 128B rows: chunk c (0..7)
__device__ __forceinline__ uint32_t swz128(int row, int c) {
    return (uint32_t)(row * 128 + ((c ^ (row & 7)) * 16));
}
__device__ __forceinline__ void cpa16(uint32_t dst, const void* src) {
    asm volatile("cp.async.cg.shared.global [%0], [%1], 16;"
                 :: "r"(dst), "l"(src));
}
#define CP_COMMIT()  asm volatile("cp.async.commit_group;")
#define CP_WAIT(n)   asm volatile("cp.async.wait_group %0;" :: "n"(n))

// ===========================================================================
// merged fp32 -> fp16 converts for x, Wqkv, Wo (+ RoPE freqs in block 0)
// ===========================================================================
__global__ void conv_all(const float4* __restrict__ x,
                         const float4* __restrict__ wq,
                         const float4* __restrict__ wo,
                         uint2* __restrict__ xh, uint2* __restrict__ wqh,
                         uint2* __restrict__ woh,
                         int n4x, int n4wq, int n4wo)
{
    if (blockIdx.x == 0 && threadIdx.x < 32)
        g_freq[threadIdx.x] =
            (float)exp(-(double)threadIdx.x * (9.210340371976184 / 32.0));

    int i = blockIdx.x * blockDim.x + threadIdx.x;
    const float4* src; uint2* dst; int idx;
    if (i < n4x)                 { src = x;  dst = xh;  idx = i; }
    else if (i < n4x + n4wq)     { src = wq; dst = wqh; idx = i - n4x; }
    else if (i < n4x + n4wq + n4wo) { src = wo; dst = woh; idx = i - n4x - n4wq; }
    else return;
    float4 v = src[idx];
    dst[idx] = make_uint2(packh2(v.x, v.y), packh2(v.z, v.w));
}

// ===========================================================================
// fp16 GEMM (R13/R14 proven): 256 thr / 8 warps, warp tile 32x64, K-chunk 64
// per stage (128B rows), 3-stage cp.async ring, occ 2. m_off for row-split.
// EPI==0: fused QKV epilogue — RoPE(Q,K) -> fp16 (Q *0.125), V -> fp16.
// EPI==1: fp32 C.
// ===========================================================================
#define GSTG 32768
#define GK_SMEM (3*GSTG)     // 98304

template<int EPI>
__global__ __launch_bounds__(256, 2) void gemm_f16(
    const __half* __restrict__ A, const __half* __restrict__ W,
    const float* __restrict__ bias, const int* __restrict__ posp,
    float* __restrict__ C, int N, int K, int m_off)
{
    extern __shared__ char smc[];
    const uint32_t sb = smem_u32(smc);

    const int tid  = threadIdx.x;
    const int warp = tid >> 5, lane = tid & 31;
    const int wm = warp & 3, cg = warp >> 2;
    const int m0 = blockIdx.y * 128 + m_off, n0 = blockIdx.x * 128;

    uint32_t offs[4];
    const __half* pA[4];
    const __half* pW[4];
    #pragma unroll
    for (int j = 0; j < 4; j++) {
        int idx = tid + j * 256;
        int row = idx >> 3, c = idx & 7;
        offs[j] = swz128(row, c);
        pA[j] = A + (size_t)(m0 + row) * K + c * 8;
        pW[j] = W + (size_t)(n0 + row) * K + c * 8;
    }

    float acc[2][8][4];
    #pragma unroll
    for (int mt = 0; mt < 2; mt++)
        #pragma unroll
        for (int nt = 0; nt < 8; nt++)
            #pragma unroll
            for (int i = 0; i < 4; i++) acc[mt][nt][i] = 0.f;

    uint32_t aOff[4][2], bOff[4][4];
    #pragma unroll
    for (int kc = 0; kc < 4; kc++) {
        #pragma unroll
        for (int mt = 0; mt < 2; mt++) {
            int r = wm * 32 + mt * 16 + (lane & 15);
            int c = kc * 2 + ((lane >> 4) & 1);
            aOff[kc][mt] = swz128(r, c);
        }
        #pragma unroll
        for (int ntp = 0; ntp < 4; ntp++) {
            int r = cg * 64 + ntp * 16 + (lane & 7) + ((lane >> 4) & 1) * 8;
            int c = kc * 2 + ((lane >> 3) & 1);
            bOff[kc][ntp] = swz128(r, c);
        }
    }

    const int NSTG = K / 64;

    auto issue = [&](int s) {
        const uint32_t base = sb + (s % 3) * GSTG;
        const int k0 = s * 64;
        #pragma unroll
        for (int j = 0; j < 4; j++) {
            cpa16(base + offs[j],         pA[j] + k0);
            cpa16(base + 16384 + offs[j], pW[j] + k0);
        }
    };

    issue(0); CP_COMMIT();
    issue(1); CP_COMMIT();

    for (int s = 0; s < NSTG; s++) {
        if (s + 1 < NSTG) { CP_WAIT(1); } else { CP_WAIT(0); }
        __syncthreads();
        if (s + 2 < NSTG) { issue(s + 2); CP_COMMIT(); }

        const uint32_t base = sb + (s % 3) * GSTG;
        #pragma unroll
        for (int kc = 0; kc < 4; kc++) {
            uint32_t a0[4], a1[4];
            ldmx4(base + aOff[kc][0], a0);
            ldmx4(base + aOff[kc][1], a1);
            #pragma unroll
            for (int ntp = 0; ntp < 4; ntp++) {
                uint32_t bfr[4];
                ldmx4(base + 16384 + bOff[kc][ntp], bfr);
                mma16816(acc[0][2*ntp],   a0, bfr[0], bfr[1]);
                mma16816(acc[0][2*ntp+1], a0, bfr[2], bfr[3]);
                mma16816(acc[1][2*ntp],   a1, bfr[0], bfr[1]);
                mma16816(acc[1][2*ntp+1], a1, bfr[2], bfr[3]);
            }
        }
    }

    // ---------------- epilogue ---------------------------------------------
    const int g = lane >> 2, tig = lane & 3;
    const int nBase = n0 + cg * 64;

    float bcol[8][2];
    #pragma unroll
    for (int nt = 0; nt < 8; nt++) {
        bcol[nt][0] = bias[nBase + nt * 8 + tig * 2];
        bcol[nt][1] = bias[nBase + nt * 8 + tig * 2 + 1];
    }

    if (EPI == 0) {
        int part = nBase >> 10;
        int hd   = (nBase & 1023) >> 6;
        if (part < 2) {
            __half* dst = part ? g_Khf : g_Qhf;
            const float sc = part ? 1.0f : 0.125f;
            float fr[4][2];
            #pragma unroll
            for (int nt = 0; nt < 4; nt++) {
                fr[nt][0] = g_freq[nt * 8 + tig * 2];
                fr[nt][1] = g_freq[nt * 8 + tig * 2 + 1];
            }
            #pragma unroll
            for (int mt = 0; mt < 2; mt++)
                #pragma unroll
                for (int half = 0; half < 2; half++) {
                    int m = m0 + wm * 32 + mt * 16 + g + half * 8;
                    int b = m >> 11, sq = m & 2047;
                    size_t rb = (((size_t)b * NH + hd) * NS + sq) * NDH;
                    float pos = (float)posp[b * NS + sq];
                    #pragma unroll
                    for (int nt = 0; nt < 4; nt++) {
                        float r1[2], r2[2];
                        #pragma unroll
                        for (int k = 0; k < 2; k++) {
                            float ang = pos * fr[nt][k];
                            float c, sn;
                            sincosf(ang, &sn, &c);
                            float q1 = acc[mt][nt][half*2 + k]   + bcol[nt][k];
                            float q2 = acc[mt][nt+4][half*2 + k] + bcol[nt+4][k];
                            r1[k] = (q1 * c + q2 * sn) * sc;
                            r2[k] = (q2 * c - q1 * sn) * sc;
                        }
                        int d = nt * 8 + tig * 2;
                        *(uint32_t*)((char*)dst + (rb + d) * 2)      = packh2(r1[0], r1[1]);
                        *(uint32_t*)((char*)dst + (rb + d + 32) * 2) = packh2(r2[0], r2[1]);
                    }
                }
        } else {
            #pragma unroll
            for (int mt = 0; mt < 2; mt++)
                #pragma unroll
                for (int half = 0; half < 2; half++) {
                    int m = m0 + wm * 32 + mt * 16 + g + half * 8;
                    int b = m >> 11, sq = m & 2047;
                    size_t rb = (((size_t)b * NH + hd) * NS + sq) * NDH;
                    #pragma unroll
                    for (int nt = 0; nt < 8; nt++) {
                        int d = nt * 8 + tig * 2;
                        float vx = acc[mt][nt][half*2]   + bcol[nt][0];
                        float vy = acc[mt][nt][half*2+1] + bcol[nt][1];
                        *(uint32_t*)((char*)g_Vhf + (rb + d) * 2) = packh2(vx, vy);
                    }
                }
        }
    } else {
        #pragma unroll
        for (int mt = 0; mt < 2; mt++)
            #pragma unroll
            for (int half = 0; half < 2; half++) {
                int m = m0 + wm * 32 + mt * 16 + g + half * 8;
                #pragma unroll
                for (int nt = 0; nt < 8; nt++) {
                    int n = nBase + nt * 8 + tig * 2;
                    float2 v;
                    v.x = acc[mt][nt][half*2]   + bcol[nt][0];
                    v.y = acc[mt][nt][half*2+1] + bcol[nt][1];
                    *(float2*)(C + (size_t)m * N + n) = v;
                }
            }
    }
}

// ===========================================================================
// fp16 flash attention (R15 proven): hoisted Q frags, double KV stages,
// ILP-interleaved softmax, vote-skip rescale. bh0 = batch-half offset.
// ===========================================================================
#define AQ 0
#define ASTG_BASE 16384
#define ASTG 32768                       // 2 tiles: K0|V0|K1|V1 (8KB each)
#define AT_SMEM (ASTG_BASE + 3*ASTG)     // 114688
#define ONESH2 0x3C003C00u               // half2(1.0, 1.0)
#define NT2 (NS/128)                     // 16 double-tile iterations

__global__ __launch_bounds__(128, 2) void attn_f16(int bh0)
{
    extern __shared__ char sma[];
    const uint32_t sb = smem_u32(sma);

    const int tid = threadIdx.x;
    const int warp = tid >> 5, lane = tid & 31;
    const int qt = blockIdx.x, bh = blockIdx.y + bh0;

    const size_t qbase  = ((size_t)bh * NS + qt * 128) * NDH;
    const size_t kvbase = (size_t)bh * NS * NDH;

    {
        #pragma unroll
        for (int j = 0; j < 8; j++) {
            int idx = tid + j * 128;
            int row = idx >> 3, c = idx & 7;
            cpa16(sb + AQ + swz128(row, c), g_Qhf + qbase + (size_t)row * NDH + c * 8);
        }
        CP_COMMIT();
    }

    const int rKV = tid >> 3, cKV = tid & 7;
    auto issue_kv2 = [&](int it) {
        const uint32_t base = sb + ASTG_BASE + (it % 3) * ASTG;
        #pragma unroll
        for (int sub = 0; sub < 2; sub++) {
            const uint32_t tb = base + sub * 16384;
            const int kt = it * 2 + sub;
            #pragma unroll
            for (int j = 0; j < 4; j++) {
                int row = rKV + j * 16;
                uint32_t o = swz128(row, cKV);
                size_t go = kvbase + (size_t)(kt * 64 + row) * NDH + cKV * 8;
                cpa16(tb + o,        g_Khf + go);
                cpa16(tb + 8192 + o, g_Vhf + go);
            }
        }
    };
    issue_kv2(0); CP_COMMIT();
    issue_kv2(1); CP_COMMIT();

    uint32_t qOff[4][2];
    #pragma unroll
    for (int kc = 0; kc < 4; kc++)
        #pragma unroll
        for (int mt = 0; mt < 2; mt++) {
            int r = warp * 32 + mt * 16 + (lane & 15);
            int c = kc * 2 + ((lane >> 4) & 1);
            qOff[kc][mt] = swz128(r, c);
        }
    uint32_t kOff[4][4];
    #pragma unroll
    for (int kc = 0; kc < 4; kc++)
        #pragma unroll
        for (int ntp = 0; ntp < 4; ntp++) {
            int r = ntp * 16 + (lane & 7) + ((lane >> 4) & 1) * 8;
            int c = kc * 2 + ((lane >> 3) & 1);
            kOff[kc][ntp] = swz128(r, c);
        }
    uint32_t vOff[4][4];
    #pragma unroll
    for (int kq = 0; kq < 4; kq++)
        #pragma unroll
        for (int dp = 0; dp < 4; dp++) {
            int r = kq * 16 + (lane & 7) + ((lane >> 3) & 1) * 8;
            int c = dp * 2 + ((lane >> 4) & 1);
            vOff[kq][dp] = swz128(r, c);
        }

    CP_WAIT(2);
    __syncthreads();
    uint32_t qf[4][2][4];
    #pragma unroll
    for (int kc = 0; kc < 4; kc++) {
        ldmx4(sb + AQ + qOff[kc][0], qf[kc][0]);
        ldmx4(sb + AQ + qOff[kc][1], qf[kc][1]);
    }

    float Oa[2][8][4];
    float lacc[2][4];
    float mrun[2][2];
    #pragma unroll
    for (int mt = 0; mt < 2; mt++) {
        mrun[mt][0] = -INFINITY; mrun[mt][1] = -INFINITY;
        #pragma unroll
        for (int i = 0; i < 4; i++) lacc[mt][i] = 0.f;
        #pragma unroll
        for (int dt = 0; dt < 8; dt++)
            #pragma unroll
            for (int i = 0; i < 4; i++) Oa[mt][dt][i] = 0.f;
    }

    for (int it = 0; it < NT2; it++) {
        if (it + 1 < NT2) { CP_WAIT(1); } else { CP_WAIT(0); }
        __syncthreads();
        if (it + 2 < NT2) { issue_kv2(it + 2); CP_COMMIT(); }

        const uint32_t stage = sb + ASTG_BASE + (it % 3) * ASTG;

        #pragma unroll
        for (int sub = 0; sub < 2; sub++) {
            const uint32_t kb = stage + sub * 16384;

            float S[2][8][4];
            #pragma unroll
            for (int mt = 0; mt < 2; mt++)
                #pragma unroll
                for (int nt = 0; nt < 8; nt++)
                    #pragma unroll
                    for (int i = 0; i < 4; i++) S[mt][nt][i] = 0.f;

            #pragma unroll
            for (int kc = 0; kc < 4; kc++) {
                #pragma unroll
                for (int ntp = 0; ntp < 4; ntp++) {
                    uint32_t kf[4];
                    ldmx4(kb + kOff[kc][ntp], kf);
                    mma16816(S[0][2*ntp],   qf[kc][0], kf[0], kf[1]);
                    mma16816(S[0][2*ntp+1], qf[kc][0], kf[2], kf[3]);
                    mma16816(S[1][2*ntp],   qf[kc][1], kf[0], kf[1]);
                    mma16816(S[1][2*ntp+1], qf[kc][1], kf[2], kf[3]);
                }
            }

            float mx[2][2];
            #pragma unroll
            for (int mt = 0; mt < 2; mt++) {
                float m0v = -INFINITY, m1v = -INFINITY;
                #pragma unroll
                for (int j = 0; j < 8; j++) {
                    m0v = fmaxf(m0v, fmaxf(S[mt][j][0], S[mt][j][1]));
                    m1v = fmaxf(m1v, fmaxf(S[mt][j][2], S[mt][j][3]));
                }
                mx[mt][0] = m0v; mx[mt][1] = m1v;
            }
            #pragma unroll
            for (int mt = 0; mt < 2; mt++) {
                mx[mt][0] = fmaxf(mx[mt][0], __shfl_xor_sync(0xffffffffu, mx[mt][0], 1));
                mx[mt][1] = fmaxf(mx[mt][1], __shfl_xor_sync(0xffffffffu, mx[mt][1], 1));
            }
            #pragma unroll
            for (int mt = 0; mt < 2; mt++) {
                mx[mt][0] = fmaxf(mx[mt][0], __shfl_xor_sync(0xffffffffu, mx[mt][0], 2));
                mx[mt][1] = fmaxf(mx[mt][1], __shfl_xor_sync(0xffffffffu, mx[mt][1], 2));
            }
            float nm[2][2];
            nm[0][0] = fmaxf(mrun[0][0], mx[0][0]);
            nm[0][1] = fmaxf(mrun[0][1], mx[0][1]);
            nm[1][0] = fmaxf(mrun[1][0], mx[1][0]);
            nm[1][1] = fmaxf(mrun[1][1], mx[1][1]);
            bool grew = (nm[0][0] > mrun[0][0]) || (nm[0][1] > mrun[0][1])
                     || (nm[1][0] > mrun[1][0]) || (nm[1][1] > mrun[1][1]);
            if (__any_sync(0xffffffffu, grew)) {
                float a00 = __expf(mrun[0][0] - nm[0][0]);
                float a01 = __expf(mrun[0][1] - nm[0][1]);
                float a10 = __expf(mrun[1][0] - nm[1][0]);
                float a11 = __expf(mrun[1][1] - nm[1][1]);
                #pragma unroll
                for (int dt = 0; dt < 8; dt++) {
                    Oa[0][dt][0] *= a00; Oa[0][dt][1] *= a00;
                    Oa[0][dt][2] *= a01; Oa[0][dt][3] *= a01;
                    Oa[1][dt][0] *= a10; Oa[1][dt][1] *= a10;
                    Oa[1][dt][2] *= a11; Oa[1][dt][3] *= a11;
                }
                lacc[0][0] *= a00; lacc[0][1] *= a00;
                lacc[0][2] *= a01; lacc[0][3] *= a01;
                lacc[1][0] *= a10; lacc[1][1] *= a10;
                lacc[1][2] *= a11; lacc[1][3] *= a11;
            }
            mrun[0][0] = nm[0][0]; mrun[0][1] = nm[0][1];
            mrun[1][0] = nm[1][0]; mrun[1][1] = nm[1][1];

            uint32_t P2[2][8][2];
            #pragma unroll
            for (int mt = 0; mt < 2; mt++) {
                float nb0 = nm[mt][0] * LOG2E, nb1 = nm[mt][1] * LOG2E;
                #pragma unroll
                for (int j = 0; j < 8; j++) {
                    float t0 = fmaf(S[mt][j][0], LOG2E, -nb0);
                    float t1 = fmaf(S[mt][j][1], LOG2E, -nb0);
                    P2[mt][j][0] = ex2h2(packh2(t0, t1));
                    float t2 = fmaf(S[mt][j][2], LOG2E, -nb1);
                    float t3 = fmaf(S[mt][j][3], LOG2E, -nb1);
                    P2[mt][j][1] = ex2h2(packh2(t2, t3));
                }
            }

            #pragma unroll
            for (int kq = 0; kq < 4; kq++) {
                uint32_t pa0[4] = {P2[0][2*kq][0], P2[0][2*kq][1],
                                   P2[0][2*kq+1][0], P2[0][2*kq+1][1]};
                uint32_t pa1[4] = {P2[1][2*kq][0], P2[1][2*kq][1],
                                   P2[1][2*kq+1][0], P2[1][2*kq+1][1]};
                mma16816(lacc[0], pa0, ONESH2, ONESH2);
                mma16816(lacc[1], pa1, ONESH2, ONESH2);
                #pragma unroll
                for (int dp = 0; dp < 4; dp++) {
                    uint32_t vf[4];
                    ldmx4t(kb + 8192 + vOff[kq][dp], vf);
                    mma16816(Oa[0][2*dp],   pa0, vf[0], vf[1]);
                    mma16816(Oa[0][2*dp+1], pa0, vf[2], vf[3]);
                    mma16816(Oa[1][2*dp],   pa1, vf[0], vf[1]);
                    mma16816(Oa[1][2*dp+1], pa1, vf[2], vf[3]);
                }
            }
        }
    }

    const int b = bh >> 4, h = bh & 15;
    const int g = lane >> 2, tg = lane & 3;
    #pragma unroll
    for (int mt = 0; mt < 2; mt++)
        #pragma unroll
        for (int half = 0; half < 2; half++) {
            int q = qt * 128 + warp * 32 + mt * 16 + g + half * 8;
            float inv = 1.0f / lacc[mt][half*2];
            size_t rb = ((size_t)b * NS + q) * ND + h * NDH;
            #pragma unroll
            for (int dt = 0; dt < 8; dt++) {
                float vx = Oa[mt][dt][half*2]   * inv;
                float vy = Oa[mt][dt][half*2+1] * inv;
                size_t o = rb + dt * 8 + tg * 2;
                *(uint32_t*)((char*)g_ctxhf + o * 2) = packh2(vx, vy);
            }
        }
}

// ===========================================================================
extern "C" void kernel_launch(void* const* d_in, const int* in_sizes, int n_in,
                              void* d_out, int out_size)
{
    (void)in_sizes; (void)n_in; (void)out_size;
    const float* x      = (const float*)d_in[0];
    const int*   p      = (const int*)d_in[1];
    const float* Wqkv_w = (const float*)d_in[2];
    const float* Wqkv_b = (const float*)d_in[3];
    const float* Wo_w   = (const float*)d_in[4];
    const float* Wo_b   = (const float*)d_in[5];
    float* out = (float*)d_out;

    cudaFuncSetAttribute(gemm_f16<0>,
                         cudaFuncAttributeMaxDynamicSharedMemorySize, GK_SMEM);
    cudaFuncSetAttribute(gemm_f16<1>,
                         cudaFuncAttributeMaxDynamicSharedMemorySize, GK_SMEM);
    cudaFuncSetAttribute(attn_f16,
                         cudaFuncAttributeMaxDynamicSharedMemorySize, AT_SMEM);

    __half *xh, *wqh, *woh, *ctxh;
    cudaGetSymbolAddress((void**)&xh,   g_xhf);
    cudaGetSymbolAddress((void**)&wqh,  g_wqhf);
    cudaGetSymbolAddress((void**)&woh,  g_wohf);
    cudaGetSymbolAddress((void**)&ctxh, g_ctxhf);

    cudaStream_t sA, sB;
    cudaStreamCreateWithFlags(&sA, cudaStreamNonBlocking);
    cudaStreamCreateWithFlags(&sB, cudaStreamNonBlocking);
    cudaEvent_t evG, evA, evB;
    cudaEventCreateWithFlags(&evG, cudaEventDisableTiming);
    cudaEventCreateWithFlags(&evA, cudaEventDisableTiming);
    cudaEventCreateWithFlags(&evB, cudaEventDisableTiming);

    int n4x = MT * ND / 4, n4wq = 3 * ND * ND / 4, n4wo = ND * ND / 4;
    int n4t = n4x + n4wq + n4wo;
    conv_all<<<(n4t + 255) / 256, 256>>>(
        (const float4*)x, (const float4*)Wqkv_w, (const float4*)Wo_w,
        (uint2*)xh, (uint2*)wqh, (uint2*)woh, n4x, n4wq, n4wo);

    // fork after converts: each chain runs QKV(half) -> attn(half) -> out(half)
    cudaEventRecord(evG, 0);
    cudaStreamWaitEvent(sA, evG, 0);
    cudaStreamWaitEvent(sB, evG, 0);

    dim3 gq(3 * ND / 128, 32);      // 4096 rows per half

    // chain A: batches 0,1 (rows 0..4095, bh 0..31)
    gemm_f16<0><<<gq, 256, GK_SMEM, sA>>>(xh, wqh, Wqkv_b, p, nullptr, 3 * ND, ND, 0);
    attn_f16<<<dim3(NS / 128, 32), 128, AT_SMEM, sA>>>(0);
    gemm_f16<1><<<dim3(ND / 128, 32), 256, GK_SMEM, sA>>>(
        ctxh, woh, Wo_b, nullptr, out, ND, ND, 0);
    cudaEventRecord(evA, sA);

    // chain B: batches 2,3 (rows 4096..8191, bh 32..63)
    gemm_f16<0><<<gq, 256, GK_SMEM, sB>>>(xh, wqh, Wqkv_b, p, nullptr, 3 * ND, ND, 4096);
    attn_f16<<<dim3(NS / 128, 32), 128, AT_SMEM, sB>>>(32);
    gemm_f16<1><<<dim3(ND / 128, 32), 256, GK_SMEM, sB>>>(
        ctxh, woh, Wo_b, nullptr, out, ND, ND, 4096);
    cudaEventRecord(evB, sB);

    // join
    cudaStreamWaitEvent(0, evA, 0);
    cudaStreamWaitEvent(0, evB, 0);

    cudaEventDestroy(evG);
    cudaEventDestroy(evA);
    cudaEventDestroy(evB);
    cudaStreamDestroy(sA);
    cudaStreamDestroy(sB);
}